// round 12
// baseline (speedup 1.0000x reference)
#include <cuda_runtime.h>
#include <cuda_bf16.h>
#include <cuda_fp16.h>
#include <cstdint>

// Problem constants
#define BATCH 16
#define CH    256
#define CQ    32
#define WW    2048

#define LOG2E 1.4426950408889634f

// ---------------------------------------------------------------------------
// Scratch (device globals: allocation-free per harness rules)
// ---------------------------------------------------------------------------
__device__ __half g_vh[(size_t)BATCH * CH * WW];                  // V fp16 [b][c][j]
__device__ __half g_qt[(size_t)BATCH * WW * CQ];                  // q^T fp16 [b][i][d] (pre-scaled log2e)
__device__ __half g_kt[(size_t)BATCH * WW * CQ];                  // k^T fp16
__device__ __half g_xt[(size_t)BATCH * WW * CH];                  // x^T fp16 [b][i][c]
__device__ __half g_wq[CQ * CH];                                  // weights single fp16
__device__ __half g_wk[CQ * CH];
__device__ __half g_wv[CH * CH];

// ---------------------------------------------------------------------------
// Helpers
// ---------------------------------------------------------------------------
__device__ __forceinline__ uint32_t smem_u32(const void* p) {
    uint32_t a;
    asm("{ .reg .u64 t; cvta.to.shared.u64 t, %1; cvt.u32.u64 %0, t; }" : "=r"(a) : "l"(p));
    return a;
}
__device__ __forceinline__ void ldsm_x4(uint32_t& r0, uint32_t& r1, uint32_t& r2, uint32_t& r3,
                                        uint32_t addr) {
    asm volatile("ldmatrix.sync.aligned.m8n8.x4.shared.b16 {%0,%1,%2,%3}, [%4];"
                 : "=r"(r0), "=r"(r1), "=r"(r2), "=r"(r3) : "r"(addr));
}
__device__ __forceinline__ void mma_fp16(float* c, const uint32_t* a, const uint32_t* b) {
    asm volatile(
        "mma.sync.aligned.m16n8k16.row.col.f32.f16.f16.f32 "
        "{%0,%1,%2,%3}, {%4,%5,%6,%7}, {%8,%9}, {%0,%1,%2,%3};"
        : "+f"(c[0]), "+f"(c[1]), "+f"(c[2]), "+f"(c[3])
        : "r"(a[0]), "r"(a[1]), "r"(a[2]), "r"(a[3]), "r"(b[0]), "r"(b[1]));
}
__device__ __forceinline__ void cp16(uint32_t dst, const void* src) {
    asm volatile("cp.async.ca.shared.global [%0], [%1], 16;" :: "r"(dst), "l"(src));
}
__device__ __forceinline__ uint32_t packh2(float x, float y) {
    __half2 t = __floats2half2_rn(x, y);
    return *(uint32_t*)&t;
}
__device__ __forceinline__ float ex2(float x) {
    float y;
    asm("ex2.approx.f32 %0, %1;" : "=f"(y) : "f"(x));
    return y;
}

// ---------------------------------------------------------------------------
// Convert all three weight matrices fp32 -> fp16 in one launch
// ---------------------------------------------------------------------------
__global__ __launch_bounds__(256)
void convert_weights(const float* __restrict__ wq, const float* __restrict__ wk,
                     const float* __restrict__ wv,
                     __half* __restrict__ oq, __half* __restrict__ ok,
                     __half* __restrict__ ov)
{
    int i = blockIdx.x * 256 + threadIdx.x;
    if (i < CQ * CH)            oq[i] = __float2half(wq[i]);
    else if (i < 2 * CQ * CH)   ok[i - CQ * CH] = __float2half(wk[i - CQ * CH]);
    else                        ov[i - 2 * CQ * CH] = __float2half(wv[i - 2 * CQ * CH]);
}

// ---------------------------------------------------------------------------
// x [b][c][i] fp32 -> x^T [b][i][c] single fp16 (32x32 smem tiles)
// ---------------------------------------------------------------------------
__global__ __launch_bounds__(256)
void transpose_x(const float* __restrict__ X, __half* __restrict__ XT)
{
    __shared__ float t[32][33];
    const int b = blockIdx.z;
    const int i0 = blockIdx.x * 32, c0 = blockIdx.y * 32;
    const int tx = threadIdx.x & 31, ty = threadIdx.x >> 5;
    const float* xb = X + (size_t)b * CH * WW;
    #pragma unroll
    for (int r = 0; r < 4; r++)
        t[ty + r * 8][tx] = xb[(size_t)(c0 + ty + r * 8) * WW + i0 + tx];
    __syncthreads();
    __half* o = XT + (size_t)b * WW * CH;
    #pragma unroll
    for (int r = 0; r < 4; r++) {
        int i = ty + r * 8;
        o[(size_t)(i0 + i) * CH + c0 + tx] = __float2half(t[tx][i]);
    }
}

// ---------------------------------------------------------------------------
// Q/K projection (single-term fp16): qT[b][i][d] fp16
// Q output pre-scaled by log2e (softmax uses exp2).
// ---------------------------------------------------------------------------
__global__ __launch_bounds__(256)
void proj_qk(const __half* __restrict__ WQ, const __half* __restrict__ WK,
             const float* __restrict__ BQ, const float* __restrict__ BK_,
             const __half* __restrict__ XT,
             __half* __restrict__ QT, __half* __restrict__ KT)
{
    __shared__ __half sA[32][40], sB[128][40];
    __shared__ float sc[129][33];
    const int tid = threadIdx.x, wid = tid >> 5, lane = tid & 31;
    const int b = blockIdx.z;
    const int n0 = blockIdx.x * 128;
    const bool isK = blockIdx.y == 1;
    const __half* w = isK ? WK : WQ;
    const float* bias = isK ? BK_ : BQ;
    const float oscale = isK ? 1.0f : LOG2E;
    __half* OT = (isK ? KT : QT) + (size_t)b * WW * CQ;
    const __half* xg = XT + (size_t)b * WW * CH;

    const int mw = wid & 1, nw = wid >> 1;
    const int mi = lane >> 3, row8 = lane & 7;
    const uint32_t aA = smem_u32(sA), aB = smem_u32(sB);

    float acc[4][4] = {};

    for (int kc = 0; kc < 8; kc++) {
        const int k0 = kc * 32;
        if (tid < 128) {
            int r = tid >> 2, c8 = (tid & 3) * 8;
            *(uint4*)&sA[r][c8] = *(const uint4*)(w + (size_t)r * CH + k0 + c8);
        }
        #pragma unroll
        for (int i2 = 0; i2 < 2; i2++) {
            int u = tid + 256 * i2;
            int r = u >> 2, c8 = (u & 3) * 8;
            *(uint4*)&sB[r][c8] = *(const uint4*)(xg + (size_t)(n0 + r) * CH + k0 + c8);
        }
        __syncthreads();
        #pragma unroll
        for (int kk = 0; kk < 2; kk++) {
            const int ks = kk * 16;
            uint32_t bb[8];
            #pragma unroll
            for (int q = 0; q < 2; q++) {
                uint32_t off = (uint32_t)((nw * 32 + q * 16 + (mi >> 1) * 8 + row8) * 40
                                          + ks + (mi & 1) * 8) * 2;
                ldsm_x4(bb[q*4+0], bb[q*4+1], bb[q*4+2], bb[q*4+3], aB + off);
            }
            uint32_t a4[4];
            const uint32_t offA = (uint32_t)((mw * 16 + (mi & 1) * 8 + row8) * 40
                                             + ks + (mi >> 1) * 8) * 2;
            ldsm_x4(a4[0], a4[1], a4[2], a4[3], aA + offA);
            #pragma unroll
            for (int g = 0; g < 4; g++)
                mma_fp16(acc[g], a4, &bb[g * 2]);
        }
        __syncthreads();
    }
    const int m = mw * 16 + (lane >> 2);
    #pragma unroll
    for (int g = 0; g < 4; g++) {
        int n = nw * 32 + g * 8 + (lane & 3) * 2;
        sc[n][m]         = (acc[g][0] + bias[m]) * oscale;
        sc[n + 1][m]     = (acc[g][1] + bias[m]) * oscale;
        sc[n][m + 8]     = (acc[g][2] + bias[m + 8]) * oscale;
        sc[n + 1][m + 8] = (acc[g][3] + bias[m + 8]) * oscale;
    }
    __syncthreads();
    const int n = tid >> 1, half = (tid & 1) * 16;
    #pragma unroll
    for (int j = 0; j < 16; j += 2) {
        *(__half2*)&OT[(size_t)(n0 + n) * CQ + half + j] =
            __floats2half2_rn(sc[n][half + j], sc[n][half + j + 1]);
    }
}

// ---------------------------------------------------------------------------
// V projection (single-term fp16, cp.async double-buffered)
// ---------------------------------------------------------------------------
__global__ __launch_bounds__(256)
void proj_v(const __half* __restrict__ WV, const float* __restrict__ BV,
            const __half* __restrict__ XT, __half* __restrict__ VH)
{
    __shared__ __half sA[2][128][40], sB[2][128][40];
    const int tid = threadIdx.x, wid = tid >> 5, lane = tid & 31;
    const int b = blockIdx.z, my = blockIdx.y;
    const int n0 = blockIdx.x * 128;
    const __half* xg = XT + (size_t)b * WW * CH;
    __half* vh = VH + (size_t)b * CH * WW;
    const int mw = wid & 1, nw = wid >> 1, mi = lane >> 3, row8 = lane & 7;

    auto stg = [&](int kc, int st) {
        const int k0 = kc * 32;
        #pragma unroll
        for (int i2 = 0; i2 < 2; i2++) {
            int u = tid + 256 * i2;
            int r = u >> 2, c8 = (u & 3) * 8;
            cp16(smem_u32(&sA[st][r][c8]), WV + (size_t)(my * 128 + r) * CH + k0 + c8);
            cp16(smem_u32(&sB[st][r][c8]), xg + (size_t)(n0 + r) * CH + k0 + c8);
        }
    };

    stg(0, 0);
    asm volatile("cp.async.commit_group;");

    float acc[4][4][4] = {};

    for (int kc = 0; kc < 8; kc++) {
        const int st = kc & 1;
        if (kc < 7) {
            stg(kc + 1, st ^ 1);
            asm volatile("cp.async.commit_group;");
            asm volatile("cp.async.wait_group 1;");
        } else {
            asm volatile("cp.async.wait_group 0;");
        }
        __syncthreads();
        const uint32_t aA = smem_u32(sA[st]), aB = smem_u32(sB[st]);
        #pragma unroll
        for (int kk = 0; kk < 2; kk++) {
            const int ks = kk * 16;
            uint32_t bb[8];
            #pragma unroll
            for (int q = 0; q < 2; q++) {
                uint32_t off = (uint32_t)((nw * 32 + q * 16 + (mi >> 1) * 8 + row8) * 40
                                          + ks + (mi & 1) * 8) * 2;
                ldsm_x4(bb[q*4+0], bb[q*4+1], bb[q*4+2], bb[q*4+3], aB + off);
            }
            uint32_t a[4][4];
            #pragma unroll
            for (int t = 0; t < 4; t++) {
                uint32_t off = (uint32_t)((mw * 64 + t * 16 + (mi & 1) * 8 + row8) * 40
                                          + ks + (mi >> 1) * 8) * 2;
                ldsm_x4(a[t][0], a[t][1], a[t][2], a[t][3], aA + off);
            }
            #pragma unroll
            for (int t = 0; t < 4; t++)
                #pragma unroll
                for (int g = 0; g < 4; g++)
                    mma_fp16(acc[t][g], a[t], &bb[g * 2]);
        }
        __syncthreads();
    }
    #pragma unroll
    for (int t = 0; t < 4; t++) {
        const int o = my * 128 + mw * 64 + t * 16 + (lane >> 2);
        const float b0 = BV[o], b8 = BV[o + 8];
        #pragma unroll
        for (int g = 0; g < 4; g++) {
            const int n = n0 + nw * 32 + g * 8 + (lane & 3) * 2;
            *(__half2*)&vh[(size_t)o * WW + n] =
                __floats2half2_rn(acc[t][g][0] + b0, acc[t][g][1] + b0);
            *(__half2*)&vh[(size_t)(o + 8) * WW + n] =
                __floats2half2_rn(acc[t][g][2] + b8, acc[t][g][3] + b8);
        }
    }
}

// ---------------------------------------------------------------------------
// Fused flash attention. Warp tile m=32 (i-rows) x n=64 (channels):
// 8 warps = 4 i-groups x 2 c-groups; CTA = 128 i x 128 c.
// V fragment reuse across 2 m-tiles cuts frag LDS by 40%.
// ---------------------------------------------------------------------------
#define F_VOFF  5120                 // K tile bytes (64 x pitch40 fp16)
#define F_STG   23552                // + V tile (128 x pitch72 fp16)
#define F_Q     47104                // 2 stages
#define F_SMEM  69632                // >= max(F_Q + 10240, sO 67584)

__global__ __launch_bounds__(256, 1)
void fused_attn(const __half* __restrict__ QT, const __half* __restrict__ KT,
                const __half* __restrict__ VH,
                const float* __restrict__ X, const float* __restrict__ gamma,
                float* __restrict__ OUT)
{
    extern __shared__ char smem[];
    const uint32_t sbase = smem_u32(smem);
    const int tid = threadIdx.x, wid = tid >> 5, lane = tid & 31;
    const int mi = lane >> 3, row8 = lane & 7;
    const int igrp = wid & 3;            // i-group: rows igrp*32 .. +31
    const int cgrp = wid >> 2;           // c-group: channels cgrp*64 .. +63
    const int i0 = blockIdx.x * 128;
    const int c0 = blockIdx.y * 128;
    const int b  = blockIdx.z;

    const __half* qg = QT + (size_t)b * WW * CQ;
    const __half* kg = KT + (size_t)b * WW * CQ;
    const __half* vhg = VH + (size_t)b * CH * WW + (size_t)c0 * WW;
    const float* xb = X + (size_t)b * CH * WW;
    float* ob = OUT + (size_t)b * CH * WW;

    auto stage = [&](int jt, int st) {
        const int j0 = jt * 64;
        const uint32_t sb = sbase + st * F_STG;
        {
            int r = tid >> 2, c8 = (tid & 3) * 8;
            cp16(sb + (uint32_t)(r * 40 + c8) * 2, kg + (size_t)(j0 + r) * CQ + c8);
        }
        #pragma unroll
        for (int it = 0; it < 4; it++) {
            int u = tid + 256 * it;                      // 0..1023 = 128x8 chunks
            int r = u >> 3, c8 = (u & 7) * 8;
            cp16(sb + F_VOFF + (uint32_t)(r * 72 + c8) * 2, vhg + (size_t)r * WW + j0 + c8);
        }
    };

    stage(0, 0);
    asm volatile("cp.async.commit_group;");

    // load q tile (plain stores)
    #pragma unroll
    for (int it = 0; it < 2; it++) {
        int u = tid + 256 * it;
        int r = u >> 2, c8 = (u & 3) * 8;
        *(uint4*)(smem + F_Q + (uint32_t)(r * 40 + c8) * 2) =
            *(const uint4*)(qg + (size_t)(i0 + r) * CQ + c8);
    }
    __syncthreads();

    // cache q fragments: 2 m-tiles x (k=32)
    uint32_t qa[2][8];
    #pragma unroll
    for (int mt = 0; mt < 2; mt++)
        #pragma unroll
        for (int kk = 0; kk < 2; kk++) {
            const uint32_t offA = (uint32_t)((igrp * 32 + mt * 16 + (mi & 1) * 8 + row8) * 40
                                             + kk * 16 + (mi >> 1) * 8) * 2;
            ldsm_x4(qa[mt][kk*4+0], qa[mt][kk*4+1], qa[mt][kk*4+2], qa[mt][kk*4+3],
                    sbase + F_Q + offA);
        }

    float o_[2][8][4] = {};
    float m_[2][2] = {{-1e30f, -1e30f}, {-1e30f, -1e30f}};
    float l_[2][2] = {};

    for (int jt = 0; jt < 32; jt++) {
        const int st = jt & 1;
        if (jt < 31) {
            stage(jt + 1, st ^ 1);
            asm volatile("cp.async.commit_group;");
            asm volatile("cp.async.wait_group 1;");
        } else {
            asm volatile("cp.async.wait_group 0;");
        }
        __syncthreads();

        const uint32_t aK = sbase + st * F_STG;
        const uint32_t aV = aK + F_VOFF;

        // ---- scores: 32 i x 64 j, single-term fp16 ----
        float s_[2][8][4] = {};
        #pragma unroll
        for (int kk = 0; kk < 2; kk++) {
            uint32_t bb[4][4];
            #pragma unroll
            for (int bt = 0; bt < 4; bt++) {
                uint32_t off = (uint32_t)((bt * 16 + (mi >> 1) * 8 + row8) * 40
                                          + kk * 16 + (mi & 1) * 8) * 2;
                ldsm_x4(bb[bt][0], bb[bt][1], bb[bt][2], bb[bt][3], aK + off);
            }
            #pragma unroll
            for (int mt = 0; mt < 2; mt++)
                #pragma unroll
                for (int bt = 0; bt < 4; bt++) {
                    mma_fp16(s_[mt][2*bt],   &qa[mt][kk*4], &bb[bt][0]);
                    mma_fp16(s_[mt][2*bt+1], &qa[mt][kk*4], &bb[bt][2]);
                }
        }

        // ---- online softmax (log2 domain, ex2.approx) ----
        float mn[2][2];
        #pragma unroll
        for (int mt = 0; mt < 2; mt++) {
            float ml0 = -1e30f, ml1 = -1e30f;
            #pragma unroll
            for (int nt = 0; nt < 8; nt++) {
                ml0 = fmaxf(ml0, fmaxf(s_[mt][nt][0], s_[mt][nt][1]));
                ml1 = fmaxf(ml1, fmaxf(s_[mt][nt][2], s_[mt][nt][3]));
            }
            ml0 = fmaxf(ml0, __shfl_xor_sync(0xffffffffu, ml0, 1));
            ml0 = fmaxf(ml0, __shfl_xor_sync(0xffffffffu, ml0, 2));
            ml1 = fmaxf(ml1, __shfl_xor_sync(0xffffffffu, ml1, 1));
            ml1 = fmaxf(ml1, __shfl_xor_sync(0xffffffffu, ml1, 2));
            mn[mt][0] = fmaxf(m_[mt][0], ml0);
            mn[mt][1] = fmaxf(m_[mt][1], ml1);
        }
        const bool nochg = __all_sync(0xffffffffu,
            (mn[0][0] == m_[0][0]) && (mn[0][1] == m_[0][1]) &&
            (mn[1][0] == m_[1][0]) && (mn[1][1] == m_[1][1]));

        float ls[2][2] = {};
        #pragma unroll
        for (int mt = 0; mt < 2; mt++)
            #pragma unroll
            for (int nt = 0; nt < 8; nt++) {
                s_[mt][nt][0] = ex2(s_[mt][nt][0] - mn[mt][0]);
                s_[mt][nt][1] = ex2(s_[mt][nt][1] - mn[mt][0]);
                s_[mt][nt][2] = ex2(s_[mt][nt][2] - mn[mt][1]);
                s_[mt][nt][3] = ex2(s_[mt][nt][3] - mn[mt][1]);
                ls[mt][0] += s_[mt][nt][0] + s_[mt][nt][1];
                ls[mt][1] += s_[mt][nt][2] + s_[mt][nt][3];
            }

        if (nochg) {
            #pragma unroll
            for (int mt = 0; mt < 2; mt++) {
                l_[mt][0] += ls[mt][0];
                l_[mt][1] += ls[mt][1];
            }
        } else {
            #pragma unroll
            for (int mt = 0; mt < 2; mt++) {
                const float sc0 = ex2(m_[mt][0] - mn[mt][0]);
                const float sc1 = ex2(m_[mt][1] - mn[mt][1]);
                l_[mt][0] = l_[mt][0] * sc0 + ls[mt][0];
                l_[mt][1] = l_[mt][1] * sc1 + ls[mt][1];
                #pragma unroll
                for (int nt = 0; nt < 8; nt++) {
                    o_[mt][nt][0] *= sc0;  o_[mt][nt][1] *= sc0;
                    o_[mt][nt][2] *= sc1;  o_[mt][nt][3] *= sc1;
                }
            }
        }
        #pragma unroll
        for (int mt = 0; mt < 2; mt++) {
            m_[mt][0] = mn[mt][0];
            m_[mt][1] = mn[mt][1];
        }

        // ---- pack P to fp16 (s_ dies here) ----
        uint32_t pa[2][4][4];
        #pragma unroll
        for (int mt = 0; mt < 2; mt++)
            #pragma unroll
            for (int ks = 0; ks < 4; ks++) {
                pa[mt][ks][0] = packh2(s_[mt][2*ks][0],   s_[mt][2*ks][1]);
                pa[mt][ks][1] = packh2(s_[mt][2*ks][2],   s_[mt][2*ks][3]);
                pa[mt][ks][2] = packh2(s_[mt][2*ks+1][0], s_[mt][2*ks+1][1]);
                pa[mt][ks][3] = packh2(s_[mt][2*ks+1][2], s_[mt][2*ks+1][3]);
            }

        // ---- PV: each V fragment feeds both m-tiles ----
        #pragma unroll
        for (int ks = 0; ks < 4; ks++) {
            #pragma unroll
            for (int vt = 0; vt < 4; vt++) {
                uint32_t off = (uint32_t)((cgrp * 64 + vt * 16 + (mi >> 1) * 8 + row8) * 72
                                          + ks * 16 + (mi & 1) * 8) * 2;
                uint32_t bv[4];
                ldsm_x4(bv[0], bv[1], bv[2], bv[3], aV + off);
                #pragma unroll
                for (int mt = 0; mt < 2; mt++) {
                    mma_fp16(o_[mt][2*vt],   pa[mt][ks], &bv[0]);
                    mma_fp16(o_[mt][2*vt+1], pa[mt][ks], &bv[2]);
                }
            }
        }
        __syncthreads();
    }

    // ---- epilogue: normalize, bounce through smem to [c][i], +gamma/x ----
    float inv[2][2];
    #pragma unroll
    for (int mt = 0; mt < 2; mt++) {
        float l0 = l_[mt][0], l1 = l_[mt][1];
        l0 += __shfl_xor_sync(0xffffffffu, l0, 1);
        l0 += __shfl_xor_sync(0xffffffffu, l0, 2);
        l1 += __shfl_xor_sync(0xffffffffu, l1, 1);
        l1 += __shfl_xor_sync(0xffffffffu, l1, 2);
        inv[mt][0] = 1.f / l0;
        inv[mt][1] = 1.f / l1;
    }

    float* sO = (float*)smem;            // [c 128][i 128] pitch 132
    #pragma unroll
    for (int mt = 0; mt < 2; mt++) {
        const int iA = igrp * 32 + mt * 16 + (lane >> 2);
        const int iB = iA + 8;
        #pragma unroll
        for (int nt = 0; nt < 8; nt++) {
            const int c = cgrp * 64 + nt * 8 + (lane & 3) * 2;
            sO[c * 132 + iA]       = o_[mt][nt][0] * inv[mt][0];
            sO[(c + 1) * 132 + iA] = o_[mt][nt][1] * inv[mt][0];
            sO[c * 132 + iB]       = o_[mt][nt][2] * inv[mt][1];
            sO[(c + 1) * 132 + iB] = o_[mt][nt][3] * inv[mt][1];
        }
    }
    __syncthreads();

    const float g = gamma[0];
    #pragma unroll
    for (int it = 0; it < 16; it++) {
        int u = tid + 256 * it;               // 0..4095
        int r = u >> 5, c4 = (u & 31) * 4;
        float4 v4 = *(float4*)&sO[r * 132 + c4];
        size_t go = (size_t)(c0 + r) * WW + i0 + c4;
        float4 xv = *(const float4*)(xb + go);
        v4.x = g * v4.x + xv.x;
        v4.y = g * v4.y + xv.y;
        v4.z = g * v4.z + xv.z;
        v4.w = g * v4.w + xv.w;
        *(float4*)(ob + go) = v4;
    }
}

// ---------------------------------------------------------------------------
extern "C" void kernel_launch(void* const* d_in, const int* in_sizes, int n_in,
                              void* d_out, int out_size)
{
    const float* x     = (const float*)d_in[0];
    const float* wq    = (const float*)d_in[1];
    const float* bq    = (const float*)d_in[2];
    const float* wk    = (const float*)d_in[3];
    const float* bk    = (const float*)d_in[4];
    const float* wv    = (const float*)d_in[5];
    const float* bv    = (const float*)d_in[6];
    const float* gamma = (const float*)d_in[7];
    float* out = (float*)d_out;

    __half *vh, *qt, *kt, *xt, *wqd, *wkd, *wvd;
    cudaGetSymbolAddress((void**)&vh, g_vh);
    cudaGetSymbolAddress((void**)&qt, g_qt);
    cudaGetSymbolAddress((void**)&kt, g_kt);
    cudaGetSymbolAddress((void**)&xt, g_xt);
    cudaGetSymbolAddress((void**)&wqd, g_wq);
    cudaGetSymbolAddress((void**)&wkd, g_wk);
    cudaGetSymbolAddress((void**)&wvd, g_wv);

    // 1. convert all weights to fp16 (one launch)
    convert_weights<<<(2 * CQ * CH + CH * CH) / 256, 256>>>(wq, wk, wv, wqd, wkd, wvd);

    // 2. transpose x -> single fp16 x^T
    transpose_x<<<dim3(WW / 32, CH / 32, BATCH), 256>>>(x, xt);

    // 3. q/k projections (fp16 output; q pre-scaled by log2e)
    proj_qk<<<dim3(WW / 128, 2, BATCH), 256>>>(wqd, wkd, bq, bk, xt, qt, kt);

    // 4. v projection (fp16 output, double-buffered)
    proj_v<<<dim3(WW / 128, CH / 128, BATCH), 256>>>(wvd, bv, xt, vh);

    // 5. fused attention (m32 x n64 warp tiles)
    cudaFuncSetAttribute(fused_attn, cudaFuncAttributeMaxDynamicSharedMemorySize, F_SMEM);
    fused_attn<<<dim3(WW / 128, CH / 128, BATCH), 256, F_SMEM>>>(
        qt, kt, vh, x, gamma, out);
}

// round 13
// speedup vs baseline: 1.2389x; 1.2389x over previous
#include <cuda_runtime.h>
#include <cuda_bf16.h>
#include <cuda_fp16.h>
#include <cstdint>

// Problem constants
#define BATCH 16
#define CH    256
#define CQ    32
#define WW    2048

#define LOG2E 1.4426950408889634f

// ---------------------------------------------------------------------------
// Scratch (device globals: allocation-free per harness rules)
// ---------------------------------------------------------------------------
__device__ __half g_vh[(size_t)BATCH * CH * WW];                  // V fp16 [b][c][j]
__device__ __half g_qt[(size_t)BATCH * WW * CQ];                  // q^T fp16 [b][i][d] (pre-scaled log2e)
__device__ __half g_kt[(size_t)BATCH * WW * CQ];                  // k^T fp16
__device__ __half g_xt[(size_t)BATCH * WW * CH];                  // x^T fp16 [b][i][c]
__device__ __half g_wq[CQ * CH];                                  // weights single fp16
__device__ __half g_wk[CQ * CH];
__device__ __half g_wv[CH * CH];

// ---------------------------------------------------------------------------
// Helpers
// ---------------------------------------------------------------------------
__device__ __forceinline__ uint32_t smem_u32(const void* p) {
    uint32_t a;
    asm("{ .reg .u64 t; cvta.to.shared.u64 t, %1; cvt.u32.u64 %0, t; }" : "=r"(a) : "l"(p));
    return a;
}
__device__ __forceinline__ void ldsm_x4(uint32_t& r0, uint32_t& r1, uint32_t& r2, uint32_t& r3,
                                        uint32_t addr) {
    asm volatile("ldmatrix.sync.aligned.m8n8.x4.shared.b16 {%0,%1,%2,%3}, [%4];"
                 : "=r"(r0), "=r"(r1), "=r"(r2), "=r"(r3) : "r"(addr));
}
__device__ __forceinline__ void mma_fp16(float* c, const uint32_t* a, const uint32_t* b) {
    asm volatile(
        "mma.sync.aligned.m16n8k16.row.col.f32.f16.f16.f32 "
        "{%0,%1,%2,%3}, {%4,%5,%6,%7}, {%8,%9}, {%0,%1,%2,%3};"
        : "+f"(c[0]), "+f"(c[1]), "+f"(c[2]), "+f"(c[3])
        : "r"(a[0]), "r"(a[1]), "r"(a[2]), "r"(a[3]), "r"(b[0]), "r"(b[1]));
}
__device__ __forceinline__ void cp16(uint32_t dst, const void* src) {
    asm volatile("cp.async.ca.shared.global [%0], [%1], 16;" :: "r"(dst), "l"(src));
}
__device__ __forceinline__ uint32_t packh2(float x, float y) {
    __half2 t = __floats2half2_rn(x, y);
    return *(uint32_t*)&t;
}
__device__ __forceinline__ float ex2(float x) {
    float y;
    asm("ex2.approx.f32 %0, %1;" : "=f"(y) : "f"(x));
    return y;
}

// ---------------------------------------------------------------------------
// Convert all three weight matrices fp32 -> fp16 in one launch
// ---------------------------------------------------------------------------
__global__ __launch_bounds__(256)
void convert_weights(const float* __restrict__ wq, const float* __restrict__ wk,
                     const float* __restrict__ wv,
                     __half* __restrict__ oq, __half* __restrict__ ok,
                     __half* __restrict__ ov)
{
    int i = blockIdx.x * 256 + threadIdx.x;
    if (i < CQ * CH)            oq[i] = __float2half(wq[i]);
    else if (i < 2 * CQ * CH)   ok[i - CQ * CH] = __float2half(wk[i - CQ * CH]);
    else                        ov[i - 2 * CQ * CH] = __float2half(wv[i - 2 * CQ * CH]);
}

// ---------------------------------------------------------------------------
// x [b][c][i] fp32 -> x^T [b][i][c] single fp16 (32x32 smem tiles)
// ---------------------------------------------------------------------------
__global__ __launch_bounds__(256)
void transpose_x(const float* __restrict__ X, __half* __restrict__ XT)
{
    __shared__ float t[32][33];
    const int b = blockIdx.z;
    const int i0 = blockIdx.x * 32, c0 = blockIdx.y * 32;
    const int tx = threadIdx.x & 31, ty = threadIdx.x >> 5;
    const float* xb = X + (size_t)b * CH * WW;
    #pragma unroll
    for (int r = 0; r < 4; r++)
        t[ty + r * 8][tx] = xb[(size_t)(c0 + ty + r * 8) * WW + i0 + tx];
    __syncthreads();
    __half* o = XT + (size_t)b * WW * CH;
    #pragma unroll
    for (int r = 0; r < 4; r++) {
        int i = ty + r * 8;
        o[(size_t)(i0 + i) * CH + c0 + tx] = __float2half(t[tx][i]);
    }
}

// ---------------------------------------------------------------------------
// Q/K projection (single-term fp16): qT[b][i][d] fp16
// Q output pre-scaled by log2e (softmax uses exp2).
// ---------------------------------------------------------------------------
__global__ __launch_bounds__(256)
void proj_qk(const __half* __restrict__ WQ, const __half* __restrict__ WK,
             const float* __restrict__ BQ, const float* __restrict__ BK_,
             const __half* __restrict__ XT,
             __half* __restrict__ QT, __half* __restrict__ KT)
{
    __shared__ __half sA[32][40], sB[128][40];
    __shared__ float sc[129][33];
    const int tid = threadIdx.x, wid = tid >> 5, lane = tid & 31;
    const int b = blockIdx.z;
    const int n0 = blockIdx.x * 128;
    const bool isK = blockIdx.y == 1;
    const __half* w = isK ? WK : WQ;
    const float* bias = isK ? BK_ : BQ;
    const float oscale = isK ? 1.0f : LOG2E;
    __half* OT = (isK ? KT : QT) + (size_t)b * WW * CQ;
    const __half* xg = XT + (size_t)b * WW * CH;

    const int mw = wid & 1, nw = wid >> 1;
    const int mi = lane >> 3, row8 = lane & 7;
    const uint32_t aA = smem_u32(sA), aB = smem_u32(sB);

    float acc[4][4] = {};

    for (int kc = 0; kc < 8; kc++) {
        const int k0 = kc * 32;
        if (tid < 128) {
            int r = tid >> 2, c8 = (tid & 3) * 8;
            *(uint4*)&sA[r][c8] = *(const uint4*)(w + (size_t)r * CH + k0 + c8);
        }
        #pragma unroll
        for (int i2 = 0; i2 < 2; i2++) {
            int u = tid + 256 * i2;
            int r = u >> 2, c8 = (u & 3) * 8;
            *(uint4*)&sB[r][c8] = *(const uint4*)(xg + (size_t)(n0 + r) * CH + k0 + c8);
        }
        __syncthreads();
        #pragma unroll
        for (int kk = 0; kk < 2; kk++) {
            const int ks = kk * 16;
            uint32_t bb[8];
            #pragma unroll
            for (int q = 0; q < 2; q++) {
                uint32_t off = (uint32_t)((nw * 32 + q * 16 + (mi >> 1) * 8 + row8) * 40
                                          + ks + (mi & 1) * 8) * 2;
                ldsm_x4(bb[q*4+0], bb[q*4+1], bb[q*4+2], bb[q*4+3], aB + off);
            }
            uint32_t a4[4];
            const uint32_t offA = (uint32_t)((mw * 16 + (mi & 1) * 8 + row8) * 40
                                             + ks + (mi >> 1) * 8) * 2;
            ldsm_x4(a4[0], a4[1], a4[2], a4[3], aA + offA);
            #pragma unroll
            for (int g = 0; g < 4; g++)
                mma_fp16(acc[g], a4, &bb[g * 2]);
        }
        __syncthreads();
    }
    const int m = mw * 16 + (lane >> 2);
    #pragma unroll
    for (int g = 0; g < 4; g++) {
        int n = nw * 32 + g * 8 + (lane & 3) * 2;
        sc[n][m]         = (acc[g][0] + bias[m]) * oscale;
        sc[n + 1][m]     = (acc[g][1] + bias[m]) * oscale;
        sc[n][m + 8]     = (acc[g][2] + bias[m + 8]) * oscale;
        sc[n + 1][m + 8] = (acc[g][3] + bias[m + 8]) * oscale;
    }
    __syncthreads();
    const int n = tid >> 1, half = (tid & 1) * 16;
    #pragma unroll
    for (int j = 0; j < 16; j += 2) {
        *(__half2*)&OT[(size_t)(n0 + n) * CQ + half + j] =
            __floats2half2_rn(sc[n][half + j], sc[n][half + j + 1]);
    }
}

// ---------------------------------------------------------------------------
// V projection (single-term fp16, cp.async double-buffered)
// ---------------------------------------------------------------------------
__global__ __launch_bounds__(256)
void proj_v(const __half* __restrict__ WV, const float* __restrict__ BV,
            const __half* __restrict__ XT, __half* __restrict__ VH)
{
    __shared__ __half sA[2][128][40], sB[2][128][40];
    const int tid = threadIdx.x, wid = tid >> 5, lane = tid & 31;
    const int b = blockIdx.z, my = blockIdx.y;
    const int n0 = blockIdx.x * 128;
    const __half* xg = XT + (size_t)b * WW * CH;
    __half* vh = VH + (size_t)b * CH * WW;
    const int mw = wid & 1, nw = wid >> 1, mi = lane >> 3, row8 = lane & 7;

    auto stg = [&](int kc, int st) {
        const int k0 = kc * 32;
        #pragma unroll
        for (int i2 = 0; i2 < 2; i2++) {
            int u = tid + 256 * i2;
            int r = u >> 2, c8 = (u & 3) * 8;
            cp16(smem_u32(&sA[st][r][c8]), WV + (size_t)(my * 128 + r) * CH + k0 + c8);
            cp16(smem_u32(&sB[st][r][c8]), xg + (size_t)(n0 + r) * CH + k0 + c8);
        }
    };

    stg(0, 0);
    asm volatile("cp.async.commit_group;");

    float acc[4][4][4] = {};

    for (int kc = 0; kc < 8; kc++) {
        const int st = kc & 1;
        if (kc < 7) {
            stg(kc + 1, st ^ 1);
            asm volatile("cp.async.commit_group;");
            asm volatile("cp.async.wait_group 1;");
        } else {
            asm volatile("cp.async.wait_group 0;");
        }
        __syncthreads();
        const uint32_t aA = smem_u32(sA[st]), aB = smem_u32(sB[st]);
        #pragma unroll
        for (int kk = 0; kk < 2; kk++) {
            const int ks = kk * 16;
            uint32_t bb[8];
            #pragma unroll
            for (int q = 0; q < 2; q++) {
                uint32_t off = (uint32_t)((nw * 32 + q * 16 + (mi >> 1) * 8 + row8) * 40
                                          + ks + (mi & 1) * 8) * 2;
                ldsm_x4(bb[q*4+0], bb[q*4+1], bb[q*4+2], bb[q*4+3], aB + off);
            }
            uint32_t a[4][4];
            #pragma unroll
            for (int t = 0; t < 4; t++) {
                uint32_t off = (uint32_t)((mw * 64 + t * 16 + (mi & 1) * 8 + row8) * 40
                                          + ks + (mi >> 1) * 8) * 2;
                ldsm_x4(a[t][0], a[t][1], a[t][2], a[t][3], aA + off);
            }
            #pragma unroll
            for (int t = 0; t < 4; t++)
                #pragma unroll
                for (int g = 0; g < 4; g++)
                    mma_fp16(acc[t][g], a[t], &bb[g * 2]);
        }
        __syncthreads();
    }
    #pragma unroll
    for (int t = 0; t < 4; t++) {
        const int o = my * 128 + mw * 64 + t * 16 + (lane >> 2);
        const float b0 = BV[o], b8 = BV[o + 8];
        #pragma unroll
        for (int g = 0; g < 4; g++) {
            const int n = n0 + nw * 32 + g * 8 + (lane & 3) * 2;
            *(__half2*)&vh[(size_t)o * WW + n] =
                __floats2half2_rn(acc[t][g][0] + b0, acc[t][g][1] + b0);
            *(__half2*)&vh[(size_t)(o + 8) * WW + n] =
                __floats2half2_rn(acc[t][g][2] + b8, acc[t][g][3] + b8);
        }
    }
}

// ---------------------------------------------------------------------------
// Fused flash attention (R11 configuration: m16 warp tiles, 2 CTA/SM,
// ex2.approx softmax per 64-j tile, warp-uniform rescale skip).
// CTA = (i-tile 128, channel-half 128, batch). 8 warps; warp owns 16 i-rows.
// ---------------------------------------------------------------------------
#define F_VOFF  5120                 // K tile bytes (64 x pitch40 fp16)
#define F_STG   23552                // + V tile (128 x pitch72 fp16)
#define F_Q     47104                // 2 stages
#define F_SMEM  69632                // >= max(F_Q + 10240, sO 67584)

__global__ __launch_bounds__(256, 2)
void fused_attn(const __half* __restrict__ QT, const __half* __restrict__ KT,
                const __half* __restrict__ VH,
                const float* __restrict__ X, const float* __restrict__ gamma,
                float* __restrict__ OUT)
{
    extern __shared__ char smem[];
    const uint32_t sbase = smem_u32(smem);
    const int tid = threadIdx.x, wid = tid >> 5, lane = tid & 31;
    const int mi = lane >> 3, row8 = lane & 7;
    const int i0 = blockIdx.x * 128;
    const int c0 = blockIdx.y * 128;
    const int b  = blockIdx.z;

    const __half* qg = QT + (size_t)b * WW * CQ;
    const __half* kg = KT + (size_t)b * WW * CQ;
    const __half* vhg = VH + (size_t)b * CH * WW + (size_t)c0 * WW;
    const float* xb = X + (size_t)b * CH * WW;
    float* ob = OUT + (size_t)b * CH * WW;

    auto stage = [&](int jt, int st) {
        const int j0 = jt * 64;
        const uint32_t sb = sbase + st * F_STG;
        {
            int r = tid >> 2, c8 = (tid & 3) * 8;
            cp16(sb + (uint32_t)(r * 40 + c8) * 2, kg + (size_t)(j0 + r) * CQ + c8);
        }
        #pragma unroll
        for (int it = 0; it < 4; it++) {
            int u = tid + 256 * it;                      // 0..1023 = 128x8 chunks
            int r = u >> 3, c8 = (u & 7) * 8;
            cp16(sb + F_VOFF + (uint32_t)(r * 72 + c8) * 2, vhg + (size_t)r * WW + j0 + c8);
        }
    };

    stage(0, 0);
    asm volatile("cp.async.commit_group;");

    // load q tile (plain stores)
    #pragma unroll
    for (int it = 0; it < 2; it++) {
        int u = tid + 256 * it;
        int r = u >> 2, c8 = (u & 3) * 8;
        *(uint4*)(smem + F_Q + (uint32_t)(r * 40 + c8) * 2) =
            *(const uint4*)(qg + (size_t)(i0 + r) * CQ + c8);
    }
    __syncthreads();

    // cache q fragments (loop-invariant)
    uint32_t qa[8];
    #pragma unroll
    for (int kk = 0; kk < 2; kk++) {
        const uint32_t offA = (uint32_t)((wid * 16 + (mi & 1) * 8 + row8) * 40
                                         + kk * 16 + (mi >> 1) * 8) * 2;
        ldsm_x4(qa[kk*4+0], qa[kk*4+1], qa[kk*4+2], qa[kk*4+3], sbase + F_Q + offA);
    }

    float o_[16][4] = {};
    float m0 = -1e30f, m1 = -1e30f, l0 = 0.f, l1 = 0.f;

    for (int jt = 0; jt < 32; jt++) {
        const int st = jt & 1;
        if (jt < 31) {
            stage(jt + 1, st ^ 1);
            asm volatile("cp.async.commit_group;");
            asm volatile("cp.async.wait_group 1;");
        } else {
            asm volatile("cp.async.wait_group 0;");
        }
        __syncthreads();

        const uint32_t aK = sbase + st * F_STG;
        const uint32_t aV = aK + F_VOFF;

        // ---- scores for all 64 j: single-term fp16 ----
        float s_[8][4] = {};
        #pragma unroll
        for (int kk = 0; kk < 2; kk++) {
            #pragma unroll
            for (int ntp = 0; ntp < 4; ntp++) {
                uint32_t off = (uint32_t)((ntp * 16 + (mi >> 1) * 8 + row8) * 40
                                          + kk * 16 + (mi & 1) * 8) * 2;
                uint32_t bk[4];
                ldsm_x4(bk[0], bk[1], bk[2], bk[3], aK + off);
                mma_fp16(s_[2*ntp],   &qa[kk*4], &bk[0]);
                mma_fp16(s_[2*ntp+1], &qa[kk*4], &bk[2]);
            }
        }

        // ---- online softmax over 64 j (log2 domain, ex2.approx) ----
        float ml0 = -1e30f, ml1 = -1e30f;
        #pragma unroll
        for (int nt = 0; nt < 8; nt++) {
            ml0 = fmaxf(ml0, fmaxf(s_[nt][0], s_[nt][1]));
            ml1 = fmaxf(ml1, fmaxf(s_[nt][2], s_[nt][3]));
        }
        ml0 = fmaxf(ml0, __shfl_xor_sync(0xffffffffu, ml0, 1));
        ml0 = fmaxf(ml0, __shfl_xor_sync(0xffffffffu, ml0, 2));
        ml1 = fmaxf(ml1, __shfl_xor_sync(0xffffffffu, ml1, 1));
        ml1 = fmaxf(ml1, __shfl_xor_sync(0xffffffffu, ml1, 2));
        const float mn0 = fmaxf(m0, ml0), mn1 = fmaxf(m1, ml1);
        const bool nochg = __all_sync(0xffffffffu, (mn0 == m0) && (mn1 == m1));

        float ls0 = 0.f, ls1 = 0.f;
        #pragma unroll
        for (int nt = 0; nt < 8; nt++) {
            s_[nt][0] = ex2(s_[nt][0] - mn0);
            s_[nt][1] = ex2(s_[nt][1] - mn0);
            s_[nt][2] = ex2(s_[nt][2] - mn1);
            s_[nt][3] = ex2(s_[nt][3] - mn1);
            ls0 += s_[nt][0] + s_[nt][1];
            ls1 += s_[nt][2] + s_[nt][3];
        }

        if (nochg) {
            l0 += ls0;
            l1 += ls1;
        } else {
            const float sc0 = ex2(m0 - mn0), sc1 = ex2(m1 - mn1);
            l0 = l0 * sc0 + ls0;
            l1 = l1 * sc1 + ls1;
            #pragma unroll
            for (int nt = 0; nt < 16; nt++) {
                o_[nt][0] *= sc0;  o_[nt][1] *= sc0;
                o_[nt][2] *= sc1;  o_[nt][3] *= sc1;
            }
        }
        m0 = mn0; m1 = mn1;

        // ---- PV: O += P(fp16) V(fp16), single term, 4 k-steps ----
        #pragma unroll
        for (int ks = 0; ks < 4; ks++) {
            uint32_t pa[4];
            pa[0] = packh2(s_[2*ks][0],   s_[2*ks][1]);
            pa[1] = packh2(s_[2*ks][2],   s_[2*ks][3]);
            pa[2] = packh2(s_[2*ks+1][0], s_[2*ks+1][1]);
            pa[3] = packh2(s_[2*ks+1][2], s_[2*ks+1][3]);
            #pragma unroll
            for (int ntp = 0; ntp < 8; ntp++) {
                uint32_t off = (uint32_t)((ntp * 16 + (mi >> 1) * 8 + row8) * 72
                                          + ks * 16 + (mi & 1) * 8) * 2;
                uint32_t bv[4];
                ldsm_x4(bv[0], bv[1], bv[2], bv[3], aV + off);
                mma_fp16(o_[2*ntp],   pa, &bv[0]);
                mma_fp16(o_[2*ntp+1], pa, &bv[2]);
            }
        }
        __syncthreads();
    }

    // ---- epilogue: normalize, bounce through smem to [c][i], +gamma/x ----
    l0 += __shfl_xor_sync(0xffffffffu, l0, 1);
    l0 += __shfl_xor_sync(0xffffffffu, l0, 2);
    l1 += __shfl_xor_sync(0xffffffffu, l1, 1);
    l1 += __shfl_xor_sync(0xffffffffu, l1, 2);
    const float inv0 = 1.f / l0, inv1 = 1.f / l1;

    float* sO = (float*)smem;            // [c 128][i 128] pitch 132
    const int rA = wid * 16 + (lane >> 2), rB = rA + 8;
    #pragma unroll
    for (int nt = 0; nt < 16; nt++) {
        const int c = nt * 8 + (lane & 3) * 2;
        sO[c * 132 + rA]       = o_[nt][0] * inv0;
        sO[(c + 1) * 132 + rA] = o_[nt][1] * inv0;
        sO[c * 132 + rB]       = o_[nt][2] * inv1;
        sO[(c + 1) * 132 + rB] = o_[nt][3] * inv1;
    }
    __syncthreads();

    const float g = gamma[0];
    #pragma unroll
    for (int it = 0; it < 16; it++) {
        int u = tid + 256 * it;               // 0..4095
        int r = u >> 5, c4 = (u & 31) * 4;
        float4 v4 = *(float4*)&sO[r * 132 + c4];
        size_t go = (size_t)(c0 + r) * WW + i0 + c4;
        float4 xv = *(const float4*)(xb + go);
        v4.x = g * v4.x + xv.x;
        v4.y = g * v4.y + xv.y;
        v4.z = g * v4.z + xv.z;
        v4.w = g * v4.w + xv.w;
        *(float4*)(ob + go) = v4;
    }
}

// ---------------------------------------------------------------------------
extern "C" void kernel_launch(void* const* d_in, const int* in_sizes, int n_in,
                              void* d_out, int out_size)
{
    const float* x     = (const float*)d_in[0];
    const float* wq    = (const float*)d_in[1];
    const float* bq    = (const float*)d_in[2];
    const float* wk    = (const float*)d_in[3];
    const float* bk    = (const float*)d_in[4];
    const float* wv    = (const float*)d_in[5];
    const float* bv    = (const float*)d_in[6];
    const float* gamma = (const float*)d_in[7];
    float* out = (float*)d_out;

    __half *vh, *qt, *kt, *xt, *wqd, *wkd, *wvd;
    cudaGetSymbolAddress((void**)&vh, g_vh);
    cudaGetSymbolAddress((void**)&qt, g_qt);
    cudaGetSymbolAddress((void**)&kt, g_kt);
    cudaGetSymbolAddress((void**)&xt, g_xt);
    cudaGetSymbolAddress((void**)&wqd, g_wq);
    cudaGetSymbolAddress((void**)&wkd, g_wk);
    cudaGetSymbolAddress((void**)&wvd, g_wv);

    // 1. convert all weights to fp16 (one launch)
    convert_weights<<<(2 * CQ * CH + CH * CH) / 256, 256>>>(wq, wk, wv, wqd, wkd, wvd);

    // 2. transpose x -> single fp16 x^T
    transpose_x<<<dim3(WW / 32, CH / 32, BATCH), 256>>>(x, xt);

    // 3. q/k projections (fp16 output; q pre-scaled by log2e)
    proj_qk<<<dim3(WW / 128, 2, BATCH), 256>>>(wqd, wkd, bq, bk, xt, qt, kt);

    // 4. v projection (fp16 output, double-buffered)
    proj_v<<<dim3(WW / 128, CH / 128, BATCH), 256>>>(wvd, bv, xt, vh);

    // 5. fused attention (R11 config: m16 tiles, 2 CTAs/SM)
    cudaFuncSetAttribute(fused_attn, cudaFuncAttributeMaxDynamicSharedMemorySize, F_SMEM);
    fused_attn<<<dim3(WW / 128, CH / 128, BATCH), 256, F_SMEM>>>(
        qt, kt, vh, x, gamma, out);
}

// round 14
// speedup vs baseline: 1.3327x; 1.0757x over previous
#include <cuda_runtime.h>
#include <cuda_bf16.h>
#include <cuda_fp16.h>
#include <cstdint>

// Problem constants
#define BATCH 16
#define CH    256
#define CQ    32
#define WW    2048

#define LOG2E 1.4426950408889634f

// ---------------------------------------------------------------------------
// Scratch (device globals: allocation-free per harness rules)
// ---------------------------------------------------------------------------
__device__ __half g_vh[(size_t)BATCH * CH * WW];                  // V fp16 [b][c][j]
__device__ __half g_qt[(size_t)BATCH * WW * CQ];                  // q^T fp16 [b][i][d] (pre-scaled log2e)
__device__ __half g_kt[(size_t)BATCH * WW * CQ];                  // k^T fp16
__device__ __half g_xt[(size_t)BATCH * WW * CH];                  // x^T fp16 [b][i][c]
__device__ __half g_wq[CQ * CH];                                  // weights single fp16
__device__ __half g_wk[CQ * CH];
__device__ __half g_wv[CH * CH];

// ---------------------------------------------------------------------------
// Helpers
// ---------------------------------------------------------------------------
__device__ __forceinline__ uint32_t smem_u32(const void* p) {
    uint32_t a;
    asm("{ .reg .u64 t; cvta.to.shared.u64 t, %1; cvt.u32.u64 %0, t; }" : "=r"(a) : "l"(p));
    return a;
}
__device__ __forceinline__ void ldsm_x4(uint32_t& r0, uint32_t& r1, uint32_t& r2, uint32_t& r3,
                                        uint32_t addr) {
    asm volatile("ldmatrix.sync.aligned.m8n8.x4.shared.b16 {%0,%1,%2,%3}, [%4];"
                 : "=r"(r0), "=r"(r1), "=r"(r2), "=r"(r3) : "r"(addr));
}
__device__ __forceinline__ void mma_fp16(float* c, const uint32_t* a, const uint32_t* b) {
    asm volatile(
        "mma.sync.aligned.m16n8k16.row.col.f32.f16.f16.f32 "
        "{%0,%1,%2,%3}, {%4,%5,%6,%7}, {%8,%9}, {%0,%1,%2,%3};"
        : "+f"(c[0]), "+f"(c[1]), "+f"(c[2]), "+f"(c[3])
        : "r"(a[0]), "r"(a[1]), "r"(a[2]), "r"(a[3]), "r"(b[0]), "r"(b[1]));
}
__device__ __forceinline__ void cp16(uint32_t dst, const void* src) {
    asm volatile("cp.async.ca.shared.global [%0], [%1], 16;" :: "r"(dst), "l"(src));
}
// pack (lo, hi) fp32 pair -> f16x2 (PTX cvt packs first src into high half)
__device__ __forceinline__ uint32_t cvt_f16x2(float lo, float hi) {
    uint32_t d;
    asm("cvt.rn.f16x2.f32 %0, %1, %2;" : "=r"(d) : "f"(hi), "f"(lo));
    return d;
}
__device__ __forceinline__ uint32_t ex2_f16x2(uint32_t x) {
    uint32_t y;
    asm("ex2.approx.f16x2 %0, %1;" : "=r"(y) : "r"(x));
    return y;
}
__device__ __forceinline__ float ex2(float x) {
    float y;
    asm("ex2.approx.f32 %0, %1;" : "=f"(y) : "f"(x));
    return y;
}

// ---------------------------------------------------------------------------
// Convert all three weight matrices fp32 -> fp16 in one launch
// ---------------------------------------------------------------------------
__global__ __launch_bounds__(256)
void convert_weights(const float* __restrict__ wq, const float* __restrict__ wk,
                     const float* __restrict__ wv,
                     __half* __restrict__ oq, __half* __restrict__ ok,
                     __half* __restrict__ ov)
{
    int i = blockIdx.x * 256 + threadIdx.x;
    if (i < CQ * CH)            oq[i] = __float2half(wq[i]);
    else if (i < 2 * CQ * CH)   ok[i - CQ * CH] = __float2half(wk[i - CQ * CH]);
    else                        ov[i - 2 * CQ * CH] = __float2half(wv[i - 2 * CQ * CH]);
}

// ---------------------------------------------------------------------------
// x [b][c][i] fp32 -> x^T [b][i][c] single fp16 (32x32 smem tiles)
// ---------------------------------------------------------------------------
__global__ __launch_bounds__(256)
void transpose_x(const float* __restrict__ X, __half* __restrict__ XT)
{
    __shared__ float t[32][33];
    const int b = blockIdx.z;
    const int i0 = blockIdx.x * 32, c0 = blockIdx.y * 32;
    const int tx = threadIdx.x & 31, ty = threadIdx.x >> 5;
    const float* xb = X + (size_t)b * CH * WW;
    #pragma unroll
    for (int r = 0; r < 4; r++)
        t[ty + r * 8][tx] = xb[(size_t)(c0 + ty + r * 8) * WW + i0 + tx];
    __syncthreads();
    __half* o = XT + (size_t)b * WW * CH;
    #pragma unroll
    for (int r = 0; r < 4; r++) {
        int i = ty + r * 8;
        o[(size_t)(i0 + i) * CH + c0 + tx] = __float2half(t[tx][i]);
    }
}

// ---------------------------------------------------------------------------
// Q/K projection (single-term fp16): qT[b][i][d] fp16
// Q output pre-scaled by log2e (softmax uses exp2).
// ---------------------------------------------------------------------------
__global__ __launch_bounds__(256)
void proj_qk(const __half* __restrict__ WQ, const __half* __restrict__ WK,
             const float* __restrict__ BQ, const float* __restrict__ BK_,
             const __half* __restrict__ XT,
             __half* __restrict__ QT, __half* __restrict__ KT)
{
    __shared__ __half sA[32][40], sB[128][40];
    __shared__ float sc[129][33];
    const int tid = threadIdx.x, wid = tid >> 5, lane = tid & 31;
    const int b = blockIdx.z;
    const int n0 = blockIdx.x * 128;
    const bool isK = blockIdx.y == 1;
    const __half* w = isK ? WK : WQ;
    const float* bias = isK ? BK_ : BQ;
    const float oscale = isK ? 1.0f : LOG2E;
    __half* OT = (isK ? KT : QT) + (size_t)b * WW * CQ;
    const __half* xg = XT + (size_t)b * WW * CH;

    const int mw = wid & 1, nw = wid >> 1;
    const int mi = lane >> 3, row8 = lane & 7;
    const uint32_t aA = smem_u32(sA), aB = smem_u32(sB);

    float acc[4][4] = {};

    for (int kc = 0; kc < 8; kc++) {
        const int k0 = kc * 32;
        if (tid < 128) {
            int r = tid >> 2, c8 = (tid & 3) * 8;
            *(uint4*)&sA[r][c8] = *(const uint4*)(w + (size_t)r * CH + k0 + c8);
        }
        #pragma unroll
        for (int i2 = 0; i2 < 2; i2++) {
            int u = tid + 256 * i2;
            int r = u >> 2, c8 = (u & 3) * 8;
            *(uint4*)&sB[r][c8] = *(const uint4*)(xg + (size_t)(n0 + r) * CH + k0 + c8);
        }
        __syncthreads();
        #pragma unroll
        for (int kk = 0; kk < 2; kk++) {
            const int ks = kk * 16;
            uint32_t bb[8];
            #pragma unroll
            for (int q = 0; q < 2; q++) {
                uint32_t off = (uint32_t)((nw * 32 + q * 16 + (mi >> 1) * 8 + row8) * 40
                                          + ks + (mi & 1) * 8) * 2;
                ldsm_x4(bb[q*4+0], bb[q*4+1], bb[q*4+2], bb[q*4+3], aB + off);
            }
            uint32_t a4[4];
            const uint32_t offA = (uint32_t)((mw * 16 + (mi & 1) * 8 + row8) * 40
                                             + ks + (mi >> 1) * 8) * 2;
            ldsm_x4(a4[0], a4[1], a4[2], a4[3], aA + offA);
            #pragma unroll
            for (int g = 0; g < 4; g++)
                mma_fp16(acc[g], a4, &bb[g * 2]);
        }
        __syncthreads();
    }
    const int m = mw * 16 + (lane >> 2);
    #pragma unroll
    for (int g = 0; g < 4; g++) {
        int n = nw * 32 + g * 8 + (lane & 3) * 2;
        sc[n][m]         = (acc[g][0] + bias[m]) * oscale;
        sc[n + 1][m]     = (acc[g][1] + bias[m]) * oscale;
        sc[n][m + 8]     = (acc[g][2] + bias[m + 8]) * oscale;
        sc[n + 1][m + 8] = (acc[g][3] + bias[m + 8]) * oscale;
    }
    __syncthreads();
    const int n = tid >> 1, half = (tid & 1) * 16;
    #pragma unroll
    for (int j = 0; j < 16; j += 2) {
        *(__half2*)&OT[(size_t)(n0 + n) * CQ + half + j] =
            __floats2half2_rn(sc[n][half + j], sc[n][half + j + 1]);
    }
}

// ---------------------------------------------------------------------------
// V projection (single-term fp16, cp.async double-buffered)
// ---------------------------------------------------------------------------
__global__ __launch_bounds__(256)
void proj_v(const __half* __restrict__ WV, const float* __restrict__ BV,
            const __half* __restrict__ XT, __half* __restrict__ VH)
{
    __shared__ __half sA[2][128][40], sB[2][128][40];
    const int tid = threadIdx.x, wid = tid >> 5, lane = tid & 31;
    const int b = blockIdx.z, my = blockIdx.y;
    const int n0 = blockIdx.x * 128;
    const __half* xg = XT + (size_t)b * WW * CH;
    __half* vh = VH + (size_t)b * CH * WW;
    const int mw = wid & 1, nw = wid >> 1, mi = lane >> 3, row8 = lane & 7;

    auto stg = [&](int kc, int st) {
        const int k0 = kc * 32;
        #pragma unroll
        for (int i2 = 0; i2 < 2; i2++) {
            int u = tid + 256 * i2;
            int r = u >> 2, c8 = (u & 3) * 8;
            cp16(smem_u32(&sA[st][r][c8]), WV + (size_t)(my * 128 + r) * CH + k0 + c8);
            cp16(smem_u32(&sB[st][r][c8]), xg + (size_t)(n0 + r) * CH + k0 + c8);
        }
    };

    stg(0, 0);
    asm volatile("cp.async.commit_group;");

    float acc[4][4][4] = {};

    for (int kc = 0; kc < 8; kc++) {
        const int st = kc & 1;
        if (kc < 7) {
            stg(kc + 1, st ^ 1);
            asm volatile("cp.async.commit_group;");
            asm volatile("cp.async.wait_group 1;");
        } else {
            asm volatile("cp.async.wait_group 0;");
        }
        __syncthreads();
        const uint32_t aA = smem_u32(sA[st]), aB = smem_u32(sB[st]);
        #pragma unroll
        for (int kk = 0; kk < 2; kk++) {
            const int ks = kk * 16;
            uint32_t bb[8];
            #pragma unroll
            for (int q = 0; q < 2; q++) {
                uint32_t off = (uint32_t)((nw * 32 + q * 16 + (mi >> 1) * 8 + row8) * 40
                                          + ks + (mi & 1) * 8) * 2;
                ldsm_x4(bb[q*4+0], bb[q*4+1], bb[q*4+2], bb[q*4+3], aB + off);
            }
            uint32_t a[4][4];
            #pragma unroll
            for (int t = 0; t < 4; t++) {
                uint32_t off = (uint32_t)((mw * 64 + t * 16 + (mi & 1) * 8 + row8) * 40
                                          + ks + (mi >> 1) * 8) * 2;
                ldsm_x4(a[t][0], a[t][1], a[t][2], a[t][3], aA + off);
            }
            #pragma unroll
            for (int t = 0; t < 4; t++)
                #pragma unroll
                for (int g = 0; g < 4; g++)
                    mma_fp16(acc[t][g], a[t], &bb[g * 2]);
        }
        __syncthreads();
    }
    #pragma unroll
    for (int t = 0; t < 4; t++) {
        const int o = my * 128 + mw * 64 + t * 16 + (lane >> 2);
        const float b0 = BV[o], b8 = BV[o + 8];
        #pragma unroll
        for (int g = 0; g < 4; g++) {
            const int n = n0 + nw * 32 + g * 8 + (lane & 3) * 2;
            *(__half2*)&vh[(size_t)o * WW + n] =
                __floats2half2_rn(acc[t][g][0] + b0, acc[t][g][1] + b0);
            *(__half2*)&vh[(size_t)(o + 8) * WW + n] =
                __floats2half2_rn(acc[t][g][2] + b8, acc[t][g][3] + b8);
        }
    }
}

// ---------------------------------------------------------------------------
// Fused flash attention: m16 warp tiles, 2 CTA/SM.
// fp16 exp (ex2.approx.f16x2) produces P fragments directly;
// row-sums l via ones-MMA into a persistent C-fragment (no FADD chain,
// no epilogue shuffle reduce).
// ---------------------------------------------------------------------------
#define F_VOFF  5120                 // K tile bytes (64 x pitch40 fp16)
#define F_STG   23552                // + V tile (128 x pitch72 fp16)
#define F_Q     47104                // 2 stages
#define F_SMEM  69632                // >= max(F_Q + 10240, sO 67584)

__global__ __launch_bounds__(256, 2)
void fused_attn(const __half* __restrict__ QT, const __half* __restrict__ KT,
                const __half* __restrict__ VH,
                const float* __restrict__ X, const float* __restrict__ gamma,
                float* __restrict__ OUT)
{
    extern __shared__ char smem[];
    const uint32_t sbase = smem_u32(smem);
    const int tid = threadIdx.x, wid = tid >> 5, lane = tid & 31;
    const int mi = lane >> 3, row8 = lane & 7;
    const int i0 = blockIdx.x * 128;
    const int c0 = blockIdx.y * 128;
    const int b  = blockIdx.z;

    const __half* qg = QT + (size_t)b * WW * CQ;
    const __half* kg = KT + (size_t)b * WW * CQ;
    const __half* vhg = VH + (size_t)b * CH * WW + (size_t)c0 * WW;
    const float* xb = X + (size_t)b * CH * WW;
    float* ob = OUT + (size_t)b * CH * WW;

    auto stage = [&](int jt, int st) {
        const int j0 = jt * 64;
        const uint32_t sb = sbase + st * F_STG;
        {
            int r = tid >> 2, c8 = (tid & 3) * 8;
            cp16(sb + (uint32_t)(r * 40 + c8) * 2, kg + (size_t)(j0 + r) * CQ + c8);
        }
        #pragma unroll
        for (int it = 0; it < 4; it++) {
            int u = tid + 256 * it;                      // 0..1023 = 128x8 chunks
            int r = u >> 3, c8 = (u & 7) * 8;
            cp16(sb + F_VOFF + (uint32_t)(r * 72 + c8) * 2, vhg + (size_t)r * WW + j0 + c8);
        }
    };

    stage(0, 0);
    asm volatile("cp.async.commit_group;");

    // load q tile (plain stores)
    #pragma unroll
    for (int it = 0; it < 2; it++) {
        int u = tid + 256 * it;
        int r = u >> 2, c8 = (u & 3) * 8;
        *(uint4*)(smem + F_Q + (uint32_t)(r * 40 + c8) * 2) =
            *(const uint4*)(qg + (size_t)(i0 + r) * CQ + c8);
    }
    __syncthreads();

    // cache q fragments (loop-invariant)
    uint32_t qa[8];
    #pragma unroll
    for (int kk = 0; kk < 2; kk++) {
        const uint32_t offA = (uint32_t)((wid * 16 + (mi & 1) * 8 + row8) * 40
                                         + kk * 16 + (mi >> 1) * 8) * 2;
        ldsm_x4(qa[kk*4+0], qa[kk*4+1], qa[kk*4+2], qa[kk*4+3], sbase + F_Q + offA);
    }

    const uint32_t ONES2 = 0x3C003C00u;          // half2(1.0, 1.0)
    const uint32_t ones_b[2] = {ONES2, ONES2};   // all-ones B fragment (n8 x k16)

    float o_[16][4] = {};
    float lacc[4] = {};                          // row-sum C frag (cols identical)
    float m0 = -1e30f, m1 = -1e30f;

    for (int jt = 0; jt < 32; jt++) {
        const int st = jt & 1;
        if (jt < 31) {
            stage(jt + 1, st ^ 1);
            asm volatile("cp.async.commit_group;");
            asm volatile("cp.async.wait_group 1;");
        } else {
            asm volatile("cp.async.wait_group 0;");
        }
        __syncthreads();

        const uint32_t aK = sbase + st * F_STG;
        const uint32_t aV = aK + F_VOFF;

        // ---- scores for all 64 j: single-term fp16 ----
        float s_[8][4] = {};
        #pragma unroll
        for (int kk = 0; kk < 2; kk++) {
            #pragma unroll
            for (int ntp = 0; ntp < 4; ntp++) {
                uint32_t off = (uint32_t)((ntp * 16 + (mi >> 1) * 8 + row8) * 40
                                          + kk * 16 + (mi & 1) * 8) * 2;
                uint32_t bk[4];
                ldsm_x4(bk[0], bk[1], bk[2], bk[3], aK + off);
                mma_fp16(s_[2*ntp],   &qa[kk*4], &bk[0]);
                mma_fp16(s_[2*ntp+1], &qa[kk*4], &bk[2]);
            }
        }

        // ---- running max (log2 domain) + rescale-skip ----
        float ml0 = -1e30f, ml1 = -1e30f;
        #pragma unroll
        for (int nt = 0; nt < 8; nt++) {
            ml0 = fmaxf(ml0, fmaxf(s_[nt][0], s_[nt][1]));
            ml1 = fmaxf(ml1, fmaxf(s_[nt][2], s_[nt][3]));
        }
        ml0 = fmaxf(ml0, __shfl_xor_sync(0xffffffffu, ml0, 1));
        ml0 = fmaxf(ml0, __shfl_xor_sync(0xffffffffu, ml0, 2));
        ml1 = fmaxf(ml1, __shfl_xor_sync(0xffffffffu, ml1, 1));
        ml1 = fmaxf(ml1, __shfl_xor_sync(0xffffffffu, ml1, 2));
        const float mn0 = fmaxf(m0, ml0), mn1 = fmaxf(m1, ml1);
        const bool nochg = __all_sync(0xffffffffu, (mn0 == m0) && (mn1 == m1));

        if (!nochg) {
            const float sc0 = ex2(m0 - mn0), sc1 = ex2(m1 - mn1);
            lacc[0] *= sc0;  lacc[1] *= sc0;
            lacc[2] *= sc1;  lacc[3] *= sc1;
            #pragma unroll
            for (int nt = 0; nt < 16; nt++) {
                o_[nt][0] *= sc0;  o_[nt][1] *= sc0;
                o_[nt][2] *= sc1;  o_[nt][3] *= sc1;
            }
        }
        m0 = mn0; m1 = mn1;

        // ---- P = exp2(s - m) via f16x2 MUFU -> A fragments directly ----
        uint32_t pa[4][4];
        #pragma unroll
        for (int ks = 0; ks < 4; ks++) {
            #pragma unroll
            for (int t = 0; t < 2; t++) {
                const int nt = 2 * ks + t;
                pa[ks][2*t]   = ex2_f16x2(cvt_f16x2(s_[nt][0] - mn0, s_[nt][1] - mn0));
                pa[ks][2*t+1] = ex2_f16x2(cvt_f16x2(s_[nt][2] - mn1, s_[nt][3] - mn1));
            }
            // row-sum accumulate: lacc += P(ks) @ ones
            mma_fp16(lacc, pa[ks], ones_b);
        }

        // ---- PV: O += P(fp16) V(fp16), 4 k-steps ----
        #pragma unroll
        for (int ks = 0; ks < 4; ks++) {
            #pragma unroll
            for (int ntp = 0; ntp < 8; ntp++) {
                uint32_t off = (uint32_t)((ntp * 16 + (mi >> 1) * 8 + row8) * 72
                                          + ks * 16 + (mi & 1) * 8) * 2;
                uint32_t bv[4];
                ldsm_x4(bv[0], bv[1], bv[2], bv[3], aV + off);
                mma_fp16(o_[2*ntp],   pa[ks], &bv[0]);
                mma_fp16(o_[2*ntp+1], pa[ks], &bv[2]);
            }
        }
        __syncthreads();
    }

    // ---- epilogue: normalize (lacc cols already hold full row sums) ----
    const float inv0 = 1.f / lacc[0], inv1 = 1.f / lacc[2];

    float* sO = (float*)smem;            // [c 128][i 128] pitch 132
    const int rA = wid * 16 + (lane >> 2), rB = rA + 8;
    #pragma unroll
    for (int nt = 0; nt < 16; nt++) {
        const int c = nt * 8 + (lane & 3) * 2;
        sO[c * 132 + rA]       = o_[nt][0] * inv0;
        sO[(c + 1) * 132 + rA] = o_[nt][1] * inv0;
        sO[c * 132 + rB]       = o_[nt][2] * inv1;
        sO[(c + 1) * 132 + rB] = o_[nt][3] * inv1;
    }
    __syncthreads();

    const float g = gamma[0];
    #pragma unroll
    for (int it = 0; it < 16; it++) {
        int u = tid + 256 * it;               // 0..4095
        int r = u >> 5, c4 = (u & 31) * 4;
        float4 v4 = *(float4*)&sO[r * 132 + c4];
        size_t go = (size_t)(c0 + r) * WW + i0 + c4;
        float4 xv = *(const float4*)(xb + go);
        v4.x = g * v4.x + xv.x;
        v4.y = g * v4.y + xv.y;
        v4.z = g * v4.z + xv.z;
        v4.w = g * v4.w + xv.w;
        *(float4*)(ob + go) = v4;
    }
}

// ---------------------------------------------------------------------------
extern "C" void kernel_launch(void* const* d_in, const int* in_sizes, int n_in,
                              void* d_out, int out_size)
{
    const float* x     = (const float*)d_in[0];
    const float* wq    = (const float*)d_in[1];
    const float* bq    = (const float*)d_in[2];
    const float* wk    = (const float*)d_in[3];
    const float* bk    = (const float*)d_in[4];
    const float* wv    = (const float*)d_in[5];
    const float* bv    = (const float*)d_in[6];
    const float* gamma = (const float*)d_in[7];
    float* out = (float*)d_out;

    __half *vh, *qt, *kt, *xt, *wqd, *wkd, *wvd;
    cudaGetSymbolAddress((void**)&vh, g_vh);
    cudaGetSymbolAddress((void**)&qt, g_qt);
    cudaGetSymbolAddress((void**)&kt, g_kt);
    cudaGetSymbolAddress((void**)&xt, g_xt);
    cudaGetSymbolAddress((void**)&wqd, g_wq);
    cudaGetSymbolAddress((void**)&wkd, g_wk);
    cudaGetSymbolAddress((void**)&wvd, g_wv);

    // 1. convert all weights to fp16 (one launch)
    convert_weights<<<(2 * CQ * CH + CH * CH) / 256, 256>>>(wq, wk, wv, wqd, wkd, wvd);

    // 2. transpose x -> single fp16 x^T
    transpose_x<<<dim3(WW / 32, CH / 32, BATCH), 256>>>(x, xt);

    // 3. q/k projections (fp16 output; q pre-scaled by log2e)
    proj_qk<<<dim3(WW / 128, 2, BATCH), 256>>>(wqd, wkd, bq, bk, xt, qt, kt);

    // 4. v projection (fp16 output, double-buffered)
    proj_v<<<dim3(WW / 128, CH / 128, BATCH), 256>>>(wvd, bv, xt, vh);

    // 5. fused attention
    cudaFuncSetAttribute(fused_attn, cudaFuncAttributeMaxDynamicSharedMemorySize, F_SMEM);
    fused_attn<<<dim3(WW / 128, CH / 128, BATCH), 256, F_SMEM>>>(
        qt, kt, vh, x, gamma, out);
}

// round 15
// speedup vs baseline: 1.3409x; 1.0062x over previous
#include <cuda_runtime.h>
#include <cuda_bf16.h>
#include <cuda_fp16.h>
#include <cstdint>

// Problem constants
#define BATCH 16
#define CH    256
#define CQ    32
#define WW    2048

#define LOG2E 1.4426950408889634f

// ---------------------------------------------------------------------------
// Scratch (device globals: allocation-free per harness rules)
// ---------------------------------------------------------------------------
__device__ __half g_vh[(size_t)BATCH * CH * WW];                  // V fp16 [b][c][j]
__device__ __half g_qt[(size_t)BATCH * WW * CQ];                  // q^T fp16 [b][i][d] (pre-scaled log2e)
__device__ __half g_kt[(size_t)BATCH * WW * CQ];                  // k^T fp16
__device__ __half g_xt[(size_t)BATCH * WW * CH];                  // x^T fp16 [b][i][c]
__device__ __half g_wq[CQ * CH];                                  // weights single fp16
__device__ __half g_wk[CQ * CH];
__device__ __half g_wv[CH * CH];

// ---------------------------------------------------------------------------
// Helpers
// ---------------------------------------------------------------------------
__device__ __forceinline__ uint32_t smem_u32(const void* p) {
    uint32_t a;
    asm("{ .reg .u64 t; cvta.to.shared.u64 t, %1; cvt.u32.u64 %0, t; }" : "=r"(a) : "l"(p));
    return a;
}
__device__ __forceinline__ void ldsm_x4(uint32_t& r0, uint32_t& r1, uint32_t& r2, uint32_t& r3,
                                        uint32_t addr) {
    asm volatile("ldmatrix.sync.aligned.m8n8.x4.shared.b16 {%0,%1,%2,%3}, [%4];"
                 : "=r"(r0), "=r"(r1), "=r"(r2), "=r"(r3) : "r"(addr));
}
__device__ __forceinline__ void mma_fp16(float* c, const uint32_t* a, const uint32_t* b) {
    asm volatile(
        "mma.sync.aligned.m16n8k16.row.col.f32.f16.f16.f32 "
        "{%0,%1,%2,%3}, {%4,%5,%6,%7}, {%8,%9}, {%0,%1,%2,%3};"
        : "+f"(c[0]), "+f"(c[1]), "+f"(c[2]), "+f"(c[3])
        : "r"(a[0]), "r"(a[1]), "r"(a[2]), "r"(a[3]), "r"(b[0]), "r"(b[1]));
}
__device__ __forceinline__ void cp16(uint32_t dst, const void* src) {
    asm volatile("cp.async.ca.shared.global [%0], [%1], 16;" :: "r"(dst), "l"(src));
}
// pack (lo, hi) fp32 pair -> f16x2 (PTX cvt packs first src into high half)
__device__ __forceinline__ uint32_t cvt_f16x2(float lo, float hi) {
    uint32_t d;
    asm("cvt.rn.f16x2.f32 %0, %1, %2;" : "=r"(d) : "f"(hi), "f"(lo));
    return d;
}
__device__ __forceinline__ uint32_t ex2_f16x2(uint32_t x) {
    uint32_t y;
    asm("ex2.approx.f16x2 %0, %1;" : "=r"(y) : "r"(x));
    return y;
}
__device__ __forceinline__ float ex2(float x) {
    float y;
    asm("ex2.approx.f32 %0, %1;" : "=f"(y) : "f"(x));
    return y;
}

// ---------------------------------------------------------------------------
// Convert all three weight matrices fp32 -> fp16 in one launch
// ---------------------------------------------------------------------------
__global__ __launch_bounds__(256)
void convert_weights(const float* __restrict__ wq, const float* __restrict__ wk,
                     const float* __restrict__ wv,
                     __half* __restrict__ oq, __half* __restrict__ ok,
                     __half* __restrict__ ov)
{
    int i = blockIdx.x * 256 + threadIdx.x;
    if (i < CQ * CH)            oq[i] = __float2half(wq[i]);
    else if (i < 2 * CQ * CH)   ok[i - CQ * CH] = __float2half(wk[i - CQ * CH]);
    else                        ov[i - 2 * CQ * CH] = __float2half(wv[i - 2 * CQ * CH]);
}

// ---------------------------------------------------------------------------
// x [b][c][i] fp32 -> x^T [b][i][c] single fp16 (32x32 smem tiles)
// ---------------------------------------------------------------------------
__global__ __launch_bounds__(256)
void transpose_x(const float* __restrict__ X, __half* __restrict__ XT)
{
    __shared__ float t[32][33];
    const int b = blockIdx.z;
    const int i0 = blockIdx.x * 32, c0 = blockIdx.y * 32;
    const int tx = threadIdx.x & 31, ty = threadIdx.x >> 5;
    const float* xb = X + (size_t)b * CH * WW;
    #pragma unroll
    for (int r = 0; r < 4; r++)
        t[ty + r * 8][tx] = xb[(size_t)(c0 + ty + r * 8) * WW + i0 + tx];
    __syncthreads();
    __half* o = XT + (size_t)b * WW * CH;
    #pragma unroll
    for (int r = 0; r < 4; r++) {
        int i = ty + r * 8;
        o[(size_t)(i0 + i) * CH + c0 + tx] = __float2half(t[tx][i]);
    }
}

// ---------------------------------------------------------------------------
// Q/K projection (single-term fp16): qT[b][i][d] fp16
// Q output pre-scaled by log2e (softmax uses exp2).
// ---------------------------------------------------------------------------
__global__ __launch_bounds__(256)
void proj_qk(const __half* __restrict__ WQ, const __half* __restrict__ WK,
             const float* __restrict__ BQ, const float* __restrict__ BK_,
             const __half* __restrict__ XT,
             __half* __restrict__ QT, __half* __restrict__ KT)
{
    __shared__ __half sA[32][40], sB[128][40];
    __shared__ float sc[129][33];
    const int tid = threadIdx.x, wid = tid >> 5, lane = tid & 31;
    const int b = blockIdx.z;
    const int n0 = blockIdx.x * 128;
    const bool isK = blockIdx.y == 1;
    const __half* w = isK ? WK : WQ;
    const float* bias = isK ? BK_ : BQ;
    const float oscale = isK ? 1.0f : LOG2E;
    __half* OT = (isK ? KT : QT) + (size_t)b * WW * CQ;
    const __half* xg = XT + (size_t)b * WW * CH;

    const int mw = wid & 1, nw = wid >> 1;
    const int mi = lane >> 3, row8 = lane & 7;
    const uint32_t aA = smem_u32(sA), aB = smem_u32(sB);

    float acc[4][4] = {};

    for (int kc = 0; kc < 8; kc++) {
        const int k0 = kc * 32;
        if (tid < 128) {
            int r = tid >> 2, c8 = (tid & 3) * 8;
            *(uint4*)&sA[r][c8] = *(const uint4*)(w + (size_t)r * CH + k0 + c8);
        }
        #pragma unroll
        for (int i2 = 0; i2 < 2; i2++) {
            int u = tid + 256 * i2;
            int r = u >> 2, c8 = (u & 3) * 8;
            *(uint4*)&sB[r][c8] = *(const uint4*)(xg + (size_t)(n0 + r) * CH + k0 + c8);
        }
        __syncthreads();
        #pragma unroll
        for (int kk = 0; kk < 2; kk++) {
            const int ks = kk * 16;
            uint32_t bb[8];
            #pragma unroll
            for (int q = 0; q < 2; q++) {
                uint32_t off = (uint32_t)((nw * 32 + q * 16 + (mi >> 1) * 8 + row8) * 40
                                          + ks + (mi & 1) * 8) * 2;
                ldsm_x4(bb[q*4+0], bb[q*4+1], bb[q*4+2], bb[q*4+3], aB + off);
            }
            uint32_t a4[4];
            const uint32_t offA = (uint32_t)((mw * 16 + (mi & 1) * 8 + row8) * 40
                                             + ks + (mi >> 1) * 8) * 2;
            ldsm_x4(a4[0], a4[1], a4[2], a4[3], aA + offA);
            #pragma unroll
            for (int g = 0; g < 4; g++)
                mma_fp16(acc[g], a4, &bb[g * 2]);
        }
        __syncthreads();
    }
    const int m = mw * 16 + (lane >> 2);
    #pragma unroll
    for (int g = 0; g < 4; g++) {
        int n = nw * 32 + g * 8 + (lane & 3) * 2;
        sc[n][m]         = (acc[g][0] + bias[m]) * oscale;
        sc[n + 1][m]     = (acc[g][1] + bias[m]) * oscale;
        sc[n][m + 8]     = (acc[g][2] + bias[m + 8]) * oscale;
        sc[n + 1][m + 8] = (acc[g][3] + bias[m + 8]) * oscale;
    }
    __syncthreads();
    const int n = tid >> 1, half = (tid & 1) * 16;
    #pragma unroll
    for (int j = 0; j < 16; j += 2) {
        *(__half2*)&OT[(size_t)(n0 + n) * CQ + half + j] =
            __floats2half2_rn(sc[n][half + j], sc[n][half + j + 1]);
    }
}

// ---------------------------------------------------------------------------
// V projection (single-term fp16, cp.async double-buffered)
// ---------------------------------------------------------------------------
__global__ __launch_bounds__(256)
void proj_v(const __half* __restrict__ WV, const float* __restrict__ BV,
            const __half* __restrict__ XT, __half* __restrict__ VH)
{
    __shared__ __half sA[2][128][40], sB[2][128][40];
    const int tid = threadIdx.x, wid = tid >> 5, lane = tid & 31;
    const int b = blockIdx.z, my = blockIdx.y;
    const int n0 = blockIdx.x * 128;
    const __half* xg = XT + (size_t)b * WW * CH;
    __half* vh = VH + (size_t)b * CH * WW;
    const int mw = wid & 1, nw = wid >> 1, mi = lane >> 3, row8 = lane & 7;

    auto stg = [&](int kc, int st) {
        const int k0 = kc * 32;
        #pragma unroll
        for (int i2 = 0; i2 < 2; i2++) {
            int u = tid + 256 * i2;
            int r = u >> 2, c8 = (u & 3) * 8;
            cp16(smem_u32(&sA[st][r][c8]), WV + (size_t)(my * 128 + r) * CH + k0 + c8);
            cp16(smem_u32(&sB[st][r][c8]), xg + (size_t)(n0 + r) * CH + k0 + c8);
        }
    };

    stg(0, 0);
    asm volatile("cp.async.commit_group;");

    float acc[4][4][4] = {};

    for (int kc = 0; kc < 8; kc++) {
        const int st = kc & 1;
        if (kc < 7) {
            stg(kc + 1, st ^ 1);
            asm volatile("cp.async.commit_group;");
            asm volatile("cp.async.wait_group 1;");
        } else {
            asm volatile("cp.async.wait_group 0;");
        }
        __syncthreads();
        const uint32_t aA = smem_u32(sA[st]), aB = smem_u32(sB[st]);
        #pragma unroll
        for (int kk = 0; kk < 2; kk++) {
            const int ks = kk * 16;
            uint32_t bb[8];
            #pragma unroll
            for (int q = 0; q < 2; q++) {
                uint32_t off = (uint32_t)((nw * 32 + q * 16 + (mi >> 1) * 8 + row8) * 40
                                          + ks + (mi & 1) * 8) * 2;
                ldsm_x4(bb[q*4+0], bb[q*4+1], bb[q*4+2], bb[q*4+3], aB + off);
            }
            uint32_t a[4][4];
            #pragma unroll
            for (int t = 0; t < 4; t++) {
                uint32_t off = (uint32_t)((mw * 64 + t * 16 + (mi & 1) * 8 + row8) * 40
                                          + ks + (mi >> 1) * 8) * 2;
                ldsm_x4(a[t][0], a[t][1], a[t][2], a[t][3], aA + off);
            }
            #pragma unroll
            for (int t = 0; t < 4; t++)
                #pragma unroll
                for (int g = 0; g < 4; g++)
                    mma_fp16(acc[t][g], a[t], &bb[g * 2]);
        }
        __syncthreads();
    }
    #pragma unroll
    for (int t = 0; t < 4; t++) {
        const int o = my * 128 + mw * 64 + t * 16 + (lane >> 2);
        const float b0 = BV[o], b8 = BV[o + 8];
        #pragma unroll
        for (int g = 0; g < 4; g++) {
            const int n = n0 + nw * 32 + g * 8 + (lane & 3) * 2;
            *(__half2*)&vh[(size_t)o * WW + n] =
                __floats2half2_rn(acc[t][g][0] + b0, acc[t][g][1] + b0);
            *(__half2*)&vh[(size_t)(o + 8) * WW + n] =
                __floats2half2_rn(acc[t][g][2] + b8, acc[t][g][3] + b8);
        }
    }
}

// ---------------------------------------------------------------------------
// Fused flash attention: m16 warp tiles, 2 CTA/SM, 3-stage cp.async ring,
// ONE __syncthreads per j-tile (trailing barrier eliminated by the ring).
// fp16 exp (ex2.approx.f16x2) -> P fragments; row sums via ones-MMA.
// ---------------------------------------------------------------------------
#define F_VOFF  5120                 // K tile bytes (64 x pitch40 fp16)
#define F_STG   23552                // + V tile (128 x pitch72 fp16)
#define F_Q     70656                // 3 stages
#define F_SMEM  80896                // F_Q + 10240 (>= sO 67584)

__global__ __launch_bounds__(256, 2)
void fused_attn(const __half* __restrict__ QT, const __half* __restrict__ KT,
                const __half* __restrict__ VH,
                const float* __restrict__ X, const float* __restrict__ gamma,
                float* __restrict__ OUT)
{
    extern __shared__ char smem[];
    const uint32_t sbase = smem_u32(smem);
    const int tid = threadIdx.x, wid = tid >> 5, lane = tid & 31;
    const int mi = lane >> 3, row8 = lane & 7;
    const int i0 = blockIdx.x * 128;
    const int c0 = blockIdx.y * 128;
    const int b  = blockIdx.z;

    const __half* qg = QT + (size_t)b * WW * CQ;
    const __half* kg = KT + (size_t)b * WW * CQ;
    const __half* vhg = VH + (size_t)b * CH * WW + (size_t)c0 * WW;
    const float* xb = X + (size_t)b * CH * WW;
    float* ob = OUT + (size_t)b * CH * WW;

    auto stage = [&](int jt, int st) {
        const int j0 = jt * 64;
        const uint32_t sb = sbase + st * F_STG;
        {
            int r = tid >> 2, c8 = (tid & 3) * 8;
            cp16(sb + (uint32_t)(r * 40 + c8) * 2, kg + (size_t)(j0 + r) * CQ + c8);
        }
        #pragma unroll
        for (int it = 0; it < 4; it++) {
            int u = tid + 256 * it;                      // 0..1023 = 128x8 chunks
            int r = u >> 3, c8 = (u & 7) * 8;
            cp16(sb + F_VOFF + (uint32_t)(r * 72 + c8) * 2, vhg + (size_t)r * WW + j0 + c8);
        }
    };

    stage(0, 0);
    asm volatile("cp.async.commit_group;");
    stage(1, 1);
    asm volatile("cp.async.commit_group;");

    // load q tile (plain stores)
    #pragma unroll
    for (int it = 0; it < 2; it++) {
        int u = tid + 256 * it;
        int r = u >> 2, c8 = (u & 3) * 8;
        *(uint4*)(smem + F_Q + (uint32_t)(r * 40 + c8) * 2) =
            *(const uint4*)(qg + (size_t)(i0 + r) * CQ + c8);
    }
    __syncthreads();

    // cache q fragments (loop-invariant)
    uint32_t qa[8];
    #pragma unroll
    for (int kk = 0; kk < 2; kk++) {
        const uint32_t offA = (uint32_t)((wid * 16 + (mi & 1) * 8 + row8) * 40
                                         + kk * 16 + (mi >> 1) * 8) * 2;
        ldsm_x4(qa[kk*4+0], qa[kk*4+1], qa[kk*4+2], qa[kk*4+3], sbase + F_Q + offA);
    }

    const uint32_t ONES2 = 0x3C003C00u;          // half2(1.0, 1.0)
    const uint32_t ones_b[2] = {ONES2, ONES2};   // all-ones B fragment (n8 x k16)

    float o_[16][4] = {};
    float lacc[4] = {};                          // row-sum C frag (cols identical)
    float m0 = -1e30f, m1 = -1e30f;

    int st = 0;
    for (int jt = 0; jt < 32; jt++) {
        if (jt < 31) {
            asm volatile("cp.async.wait_group 1;");
        } else {
            asm volatile("cp.async.wait_group 0;");
        }
        __syncthreads();                         // single barrier per iteration

        // prefetch jt+2 into the ring slot consumed two iterations ago
        if (jt < 30) {
            int st2 = st + 2; if (st2 >= 3) st2 -= 3;
            stage(jt + 2, st2);
            asm volatile("cp.async.commit_group;");
        }

        const uint32_t aK = sbase + st * F_STG;
        const uint32_t aV = aK + F_VOFF;

        // ---- scores for all 64 j: single-term fp16 ----
        float s_[8][4] = {};
        #pragma unroll
        for (int kk = 0; kk < 2; kk++) {
            #pragma unroll
            for (int ntp = 0; ntp < 4; ntp++) {
                uint32_t off = (uint32_t)((ntp * 16 + (mi >> 1) * 8 + row8) * 40
                                          + kk * 16 + (mi & 1) * 8) * 2;
                uint32_t bk[4];
                ldsm_x4(bk[0], bk[1], bk[2], bk[3], aK + off);
                mma_fp16(s_[2*ntp],   &qa[kk*4], &bk[0]);
                mma_fp16(s_[2*ntp+1], &qa[kk*4], &bk[2]);
            }
        }

        // ---- running max (log2 domain) + rescale-skip ----
        float ml0 = -1e30f, ml1 = -1e30f;
        #pragma unroll
        for (int nt = 0; nt < 8; nt++) {
            ml0 = fmaxf(ml0, fmaxf(s_[nt][0], s_[nt][1]));
            ml1 = fmaxf(ml1, fmaxf(s_[nt][2], s_[nt][3]));
        }
        ml0 = fmaxf(ml0, __shfl_xor_sync(0xffffffffu, ml0, 1));
        ml0 = fmaxf(ml0, __shfl_xor_sync(0xffffffffu, ml0, 2));
        ml1 = fmaxf(ml1, __shfl_xor_sync(0xffffffffu, ml1, 1));
        ml1 = fmaxf(ml1, __shfl_xor_sync(0xffffffffu, ml1, 2));
        const float mn0 = fmaxf(m0, ml0), mn1 = fmaxf(m1, ml1);
        const bool nochg = __all_sync(0xffffffffu, (mn0 == m0) && (mn1 == m1));

        if (!nochg) {
            const float sc0 = ex2(m0 - mn0), sc1 = ex2(m1 - mn1);
            lacc[0] *= sc0;  lacc[1] *= sc0;
            lacc[2] *= sc1;  lacc[3] *= sc1;
            #pragma unroll
            for (int nt = 0; nt < 16; nt++) {
                o_[nt][0] *= sc0;  o_[nt][1] *= sc0;
                o_[nt][2] *= sc1;  o_[nt][3] *= sc1;
            }
        }
        m0 = mn0; m1 = mn1;

        // ---- P = exp2(s - m) via f16x2 MUFU -> A fragments directly ----
        uint32_t pa[4][4];
        #pragma unroll
        for (int ks = 0; ks < 4; ks++) {
            #pragma unroll
            for (int t = 0; t < 2; t++) {
                const int nt = 2 * ks + t;
                pa[ks][2*t]   = ex2_f16x2(cvt_f16x2(s_[nt][0] - mn0, s_[nt][1] - mn0));
                pa[ks][2*t+1] = ex2_f16x2(cvt_f16x2(s_[nt][2] - mn1, s_[nt][3] - mn1));
            }
            // row-sum accumulate: lacc += P(ks) @ ones
            mma_fp16(lacc, pa[ks], ones_b);
        }

        // ---- PV: O += P(fp16) V(fp16), 4 k-steps ----
        #pragma unroll
        for (int ks = 0; ks < 4; ks++) {
            #pragma unroll
            for (int ntp = 0; ntp < 8; ntp++) {
                uint32_t off = (uint32_t)((ntp * 16 + (mi >> 1) * 8 + row8) * 72
                                          + ks * 16 + (mi & 1) * 8) * 2;
                uint32_t bv[4];
                ldsm_x4(bv[0], bv[1], bv[2], bv[3], aV + off);
                mma_fp16(o_[2*ntp],   pa[ks], &bv[0]);
                mma_fp16(o_[2*ntp+1], pa[ks], &bv[2]);
            }
        }

        if (++st == 3) st = 0;
    }

    // ---- epilogue: normalize (lacc cols already hold full row sums) ----
    const float inv0 = 1.f / lacc[0], inv1 = 1.f / lacc[2];

    __syncthreads();                             // all warps done with ring before sO reuse
    float* sO = (float*)smem;            // [c 128][i 128] pitch 132
    const int rA = wid * 16 + (lane >> 2), rB = rA + 8;
    #pragma unroll
    for (int nt = 0; nt < 16; nt++) {
        const int c = nt * 8 + (lane & 3) * 2;
        sO[c * 132 + rA]       = o_[nt][0] * inv0;
        sO[(c + 1) * 132 + rA] = o_[nt][1] * inv0;
        sO[c * 132 + rB]       = o_[nt][2] * inv1;
        sO[(c + 1) * 132 + rB] = o_[nt][3] * inv1;
    }
    __syncthreads();

    const float g = gamma[0];
    #pragma unroll
    for (int it = 0; it < 16; it++) {
        int u = tid + 256 * it;               // 0..4095
        int r = u >> 5, c4 = (u & 31) * 4;
        float4 v4 = *(float4*)&sO[r * 132 + c4];
        size_t go = (size_t)(c0 + r) * WW + i0 + c4;
        float4 xv = *(const float4*)(xb + go);
        v4.x = g * v4.x + xv.x;
        v4.y = g * v4.y + xv.y;
        v4.z = g * v4.z + xv.z;
        v4.w = g * v4.w + xv.w;
        *(float4*)(ob + go) = v4;
    }
}

// ---------------------------------------------------------------------------
extern "C" void kernel_launch(void* const* d_in, const int* in_sizes, int n_in,
                              void* d_out, int out_size)
{
    const float* x     = (const float*)d_in[0];
    const float* wq    = (const float*)d_in[1];
    const float* bq    = (const float*)d_in[2];
    const float* wk    = (const float*)d_in[3];
    const float* bk    = (const float*)d_in[4];
    const float* wv    = (const float*)d_in[5];
    const float* bv    = (const float*)d_in[6];
    const float* gamma = (const float*)d_in[7];
    float* out = (float*)d_out;

    __half *vh, *qt, *kt, *xt, *wqd, *wkd, *wvd;
    cudaGetSymbolAddress((void**)&vh, g_vh);
    cudaGetSymbolAddress((void**)&qt, g_qt);
    cudaGetSymbolAddress((void**)&kt, g_kt);
    cudaGetSymbolAddress((void**)&xt, g_xt);
    cudaGetSymbolAddress((void**)&wqd, g_wq);
    cudaGetSymbolAddress((void**)&wkd, g_wk);
    cudaGetSymbolAddress((void**)&wvd, g_wv);

    // 1. convert all weights to fp16 (one launch)
    convert_weights<<<(2 * CQ * CH + CH * CH) / 256, 256>>>(wq, wk, wv, wqd, wkd, wvd);

    // 2. transpose x -> single fp16 x^T
    transpose_x<<<dim3(WW / 32, CH / 32, BATCH), 256>>>(x, xt);

    // 3. q/k projections (fp16 output; q pre-scaled by log2e)
    proj_qk<<<dim3(WW / 128, 2, BATCH), 256>>>(wqd, wkd, bq, bk, xt, qt, kt);

    // 4. v projection (fp16 output, double-buffered)
    proj_v<<<dim3(WW / 128, CH / 128, BATCH), 256>>>(wvd, bv, xt, vh);

    // 5. fused attention (3-stage ring, single barrier per j-tile)
    cudaFuncSetAttribute(fused_attn, cudaFuncAttributeMaxDynamicSharedMemorySize, F_SMEM);
    fused_attn<<<dim3(WW / 128, CH / 128, BATCH), 256, F_SMEM>>>(
        qt, kt, vh, x, gamma, out);
}

// round 16
// speedup vs baseline: 1.3920x; 1.0381x over previous
#include <cuda_runtime.h>
#include <cuda_bf16.h>
#include <cuda_fp16.h>
#include <cstdint>

// Problem constants
#define BATCH 16
#define CH    256
#define CQ    32
#define WW    2048

#define LOG2E 1.4426950408889634f

// ---------------------------------------------------------------------------
// Scratch (device globals: allocation-free per harness rules)
// ---------------------------------------------------------------------------
__device__ __half g_vh[(size_t)BATCH * CH * WW];                  // V fp16 [b][c][j]
__device__ __half g_qt[(size_t)BATCH * WW * CQ];                  // q^T fp16 [b][i][d] (pre-scaled log2e)
__device__ __half g_kt[(size_t)BATCH * WW * CQ];                  // k^T fp16
__device__ __half g_xt[(size_t)BATCH * WW * CH];                  // x^T fp16 [b][i][c]
__device__ __half g_wq[CQ * CH];                                  // weights single fp16
__device__ __half g_wk[CQ * CH];
__device__ __half g_wv[CH * CH];

// ---------------------------------------------------------------------------
// Helpers
// ---------------------------------------------------------------------------
__device__ __forceinline__ uint32_t smem_u32(const void* p) {
    uint32_t a;
    asm("{ .reg .u64 t; cvta.to.shared.u64 t, %1; cvt.u32.u64 %0, t; }" : "=r"(a) : "l"(p));
    return a;
}
__device__ __forceinline__ void ldsm_x4(uint32_t& r0, uint32_t& r1, uint32_t& r2, uint32_t& r3,
                                        uint32_t addr) {
    asm volatile("ldmatrix.sync.aligned.m8n8.x4.shared.b16 {%0,%1,%2,%3}, [%4];"
                 : "=r"(r0), "=r"(r1), "=r"(r2), "=r"(r3) : "r"(addr));
}
__device__ __forceinline__ void mma_fp16(float* c, const uint32_t* a, const uint32_t* b) {
    asm volatile(
        "mma.sync.aligned.m16n8k16.row.col.f32.f16.f16.f32 "
        "{%0,%1,%2,%3}, {%4,%5,%6,%7}, {%8,%9}, {%0,%1,%2,%3};"
        : "+f"(c[0]), "+f"(c[1]), "+f"(c[2]), "+f"(c[3])
        : "r"(a[0]), "r"(a[1]), "r"(a[2]), "r"(a[3]), "r"(b[0]), "r"(b[1]));
}
__device__ __forceinline__ void cp16(uint32_t dst, const void* src) {
    asm volatile("cp.async.ca.shared.global [%0], [%1], 16;" :: "r"(dst), "l"(src));
}
// pack (lo, hi) fp32 pair -> f16x2 (PTX cvt packs first src into high half)
__device__ __forceinline__ uint32_t cvt_f16x2(float lo, float hi) {
    uint32_t d;
    asm("cvt.rn.f16x2.f32 %0, %1, %2;" : "=r"(d) : "f"(hi), "f"(lo));
    return d;
}
__device__ __forceinline__ uint32_t ex2_f16x2(uint32_t x) {
    uint32_t y;
    asm("ex2.approx.f16x2 %0, %1;" : "=r"(y) : "r"(x));
    return y;
}
__device__ __forceinline__ float ex2(float x) {
    float y;
    asm("ex2.approx.f32 %0, %1;" : "=f"(y) : "f"(x));
    return y;
}

// ---------------------------------------------------------------------------
// Convert all three weight matrices fp32 -> fp16 in one launch
// ---------------------------------------------------------------------------
__global__ __launch_bounds__(256)
void convert_weights(const float* __restrict__ wq, const float* __restrict__ wk,
                     const float* __restrict__ wv,
                     __half* __restrict__ oq, __half* __restrict__ ok,
                     __half* __restrict__ ov)
{
    int i = blockIdx.x * 256 + threadIdx.x;
    if (i < CQ * CH)            oq[i] = __float2half(wq[i]);
    else if (i < 2 * CQ * CH)   ok[i - CQ * CH] = __float2half(wk[i - CQ * CH]);
    else                        ov[i - 2 * CQ * CH] = __float2half(wv[i - 2 * CQ * CH]);
}

// ---------------------------------------------------------------------------
// x [b][c][i] fp32 -> x^T [b][i][c] single fp16 (32x32 smem tiles)
// ---------------------------------------------------------------------------
__global__ __launch_bounds__(256)
void transpose_x(const float* __restrict__ X, __half* __restrict__ XT)
{
    __shared__ float t[32][33];
    const int b = blockIdx.z;
    const int i0 = blockIdx.x * 32, c0 = blockIdx.y * 32;
    const int tx = threadIdx.x & 31, ty = threadIdx.x >> 5;
    const float* xb = X + (size_t)b * CH * WW;
    #pragma unroll
    for (int r = 0; r < 4; r++)
        t[ty + r * 8][tx] = xb[(size_t)(c0 + ty + r * 8) * WW + i0 + tx];
    __syncthreads();
    __half* o = XT + (size_t)b * WW * CH;
    #pragma unroll
    for (int r = 0; r < 4; r++) {
        int i = ty + r * 8;
        o[(size_t)(i0 + i) * CH + c0 + tx] = __float2half(t[tx][i]);
    }
}

// ---------------------------------------------------------------------------
// Q/K projection: single-term fp16, BK=64, cp.async 2-stage ring.
// qT[b][i][d] fp16; Q output pre-scaled by log2e.
// Dynamic smem: stage = A(32x72) + B(128x72) fp16 = 23040 B, 2 stages.
// ---------------------------------------------------------------------------
#define QK_A_B   4608                 // 32*72*2
#define QK_STG   23040                // A + B(128*72*2=18432)
#define QK_SMEM  46080

__global__ __launch_bounds__(256)
void proj_qk(const __half* __restrict__ WQ, const __half* __restrict__ WK,
             const float* __restrict__ BQ, const float* __restrict__ BK_,
             const __half* __restrict__ XT,
             __half* __restrict__ QT, __half* __restrict__ KT)
{
    extern __shared__ char dsm[];
    __shared__ float sc[129][33];
    const uint32_t sbase = smem_u32(dsm);
    const int tid = threadIdx.x, wid = tid >> 5, lane = tid & 31;
    const int b = blockIdx.z;
    const int n0 = blockIdx.x * 128;
    const bool isK = blockIdx.y == 1;
    const __half* w = isK ? WK : WQ;
    const float* bias = isK ? BK_ : BQ;
    const float oscale = isK ? 1.0f : LOG2E;
    __half* OT = (isK ? KT : QT) + (size_t)b * WW * CQ;
    const __half* xg = XT + (size_t)b * WW * CH;

    const int mw = wid & 1, nw = wid >> 1;
    const int mi = lane >> 3, row8 = lane & 7;

    auto stg = [&](int kc, int st) {
        const int k0 = kc * 64;
        const uint32_t sb = sbase + st * QK_STG;
        {
            int r = tid >> 3, c8 = (tid & 7) * 8;    // 256 = 32x8 chunks (A)
            cp16(sb + (uint32_t)(r * 72 + c8) * 2, w + (size_t)r * CH + k0 + c8);
        }
        #pragma unroll
        for (int it = 0; it < 4; it++) {
            int u = tid + 256 * it;                  // 0..1023 = 128x8 chunks (B)
            int r = u >> 3, c8 = (u & 7) * 8;
            cp16(sb + QK_A_B + (uint32_t)(r * 72 + c8) * 2,
                 xg + (size_t)(n0 + r) * CH + k0 + c8);
        }
    };

    stg(0, 0);
    asm volatile("cp.async.commit_group;");

    float acc[4][4] = {};

    for (int kc = 0; kc < 4; kc++) {
        const int st = kc & 1;
        if (kc < 3) {
            stg(kc + 1, st ^ 1);
            asm volatile("cp.async.commit_group;");
            asm volatile("cp.async.wait_group 1;");
        } else {
            asm volatile("cp.async.wait_group 0;");
        }
        __syncthreads();
        const uint32_t aA = sbase + st * QK_STG;
        const uint32_t aB = aA + QK_A_B;
        #pragma unroll
        for (int kk = 0; kk < 4; kk++) {
            const int ks = kk * 16;
            uint32_t bb[8];
            #pragma unroll
            for (int q = 0; q < 2; q++) {
                uint32_t off = (uint32_t)((nw * 32 + q * 16 + (mi >> 1) * 8 + row8) * 72
                                          + ks + (mi & 1) * 8) * 2;
                ldsm_x4(bb[q*4+0], bb[q*4+1], bb[q*4+2], bb[q*4+3], aB + off);
            }
            uint32_t a4[4];
            const uint32_t offA = (uint32_t)((mw * 16 + (mi & 1) * 8 + row8) * 72
                                             + ks + (mi >> 1) * 8) * 2;
            ldsm_x4(a4[0], a4[1], a4[2], a4[3], aA + offA);
            #pragma unroll
            for (int g = 0; g < 4; g++)
                mma_fp16(acc[g], a4, &bb[g * 2]);
        }
        __syncthreads();
    }
    const int m = mw * 16 + (lane >> 2);
    #pragma unroll
    for (int g = 0; g < 4; g++) {
        int n = nw * 32 + g * 8 + (lane & 3) * 2;
        sc[n][m]         = (acc[g][0] + bias[m]) * oscale;
        sc[n + 1][m]     = (acc[g][1] + bias[m]) * oscale;
        sc[n][m + 8]     = (acc[g][2] + bias[m + 8]) * oscale;
        sc[n + 1][m + 8] = (acc[g][3] + bias[m + 8]) * oscale;
    }
    __syncthreads();
    const int n = tid >> 1, half = (tid & 1) * 16;
    #pragma unroll
    for (int j = 0; j < 16; j += 2) {
        *(__half2*)&OT[(size_t)(n0 + n) * CQ + half + j] =
            __floats2half2_rn(sc[n][half + j], sc[n][half + j + 1]);
    }
}

// ---------------------------------------------------------------------------
// V projection: single-term fp16, BK=64, cp.async 2-stage ring.
// Dynamic smem: stage = A(128x72) + B(128x72) fp16 = 36864 B, 2 stages.
// ---------------------------------------------------------------------------
#define PV_A_B   18432                // 128*72*2
#define PV_STG   36864
#define PV_SMEM  73728

__global__ __launch_bounds__(256)
void proj_v(const __half* __restrict__ WV, const float* __restrict__ BV,
            const __half* __restrict__ XT, __half* __restrict__ VH)
{
    extern __shared__ char dsm[];
    const uint32_t sbase = smem_u32(dsm);
    const int tid = threadIdx.x, wid = tid >> 5, lane = tid & 31;
    const int b = blockIdx.z, my = blockIdx.y;
    const int n0 = blockIdx.x * 128;
    const __half* xg = XT + (size_t)b * WW * CH;
    __half* vh = VH + (size_t)b * CH * WW;
    const int mw = wid & 1, nw = wid >> 1, mi = lane >> 3, row8 = lane & 7;

    auto stg = [&](int kc, int st) {
        const int k0 = kc * 64;
        const uint32_t sb = sbase + st * PV_STG;
        #pragma unroll
        for (int it = 0; it < 4; it++) {
            int u = tid + 256 * it;                  // 0..1023 = 128x8 chunks
            int r = u >> 3, c8 = (u & 7) * 8;
            uint32_t so = (uint32_t)(r * 72 + c8) * 2;
            cp16(sb + so, WV + (size_t)(my * 128 + r) * CH + k0 + c8);
            cp16(sb + PV_A_B + so, xg + (size_t)(n0 + r) * CH + k0 + c8);
        }
    };

    stg(0, 0);
    asm volatile("cp.async.commit_group;");

    float acc[4][4][4] = {};

    for (int kc = 0; kc < 4; kc++) {
        const int st = kc & 1;
        if (kc < 3) {
            stg(kc + 1, st ^ 1);
            asm volatile("cp.async.commit_group;");
            asm volatile("cp.async.wait_group 1;");
        } else {
            asm volatile("cp.async.wait_group 0;");
        }
        __syncthreads();
        const uint32_t aA = sbase + st * PV_STG;
        const uint32_t aB = aA + PV_A_B;
        #pragma unroll
        for (int kk = 0; kk < 4; kk++) {
            const int ks = kk * 16;
            uint32_t bb[8];
            #pragma unroll
            for (int q = 0; q < 2; q++) {
                uint32_t off = (uint32_t)((nw * 32 + q * 16 + (mi >> 1) * 8 + row8) * 72
                                          + ks + (mi & 1) * 8) * 2;
                ldsm_x4(bb[q*4+0], bb[q*4+1], bb[q*4+2], bb[q*4+3], aB + off);
            }
            uint32_t a[4][4];
            #pragma unroll
            for (int t = 0; t < 4; t++) {
                uint32_t off = (uint32_t)((mw * 64 + t * 16 + (mi & 1) * 8 + row8) * 72
                                          + ks + (mi >> 1) * 8) * 2;
                ldsm_x4(a[t][0], a[t][1], a[t][2], a[t][3], aA + off);
            }
            #pragma unroll
            for (int t = 0; t < 4; t++)
                #pragma unroll
                for (int g = 0; g < 4; g++)
                    mma_fp16(acc[t][g], a[t], &bb[g * 2]);
        }
        __syncthreads();
    }
    #pragma unroll
    for (int t = 0; t < 4; t++) {
        const int o = my * 128 + mw * 64 + t * 16 + (lane >> 2);
        const float b0 = BV[o], b8 = BV[o + 8];
        #pragma unroll
        for (int g = 0; g < 4; g++) {
            const int n = n0 + nw * 32 + g * 8 + (lane & 3) * 2;
            *(__half2*)&vh[(size_t)o * WW + n] =
                __floats2half2_rn(acc[t][g][0] + b0, acc[t][g][1] + b0);
            *(__half2*)&vh[(size_t)(o + 8) * WW + n] =
                __floats2half2_rn(acc[t][g][2] + b8, acc[t][g][3] + b8);
        }
    }
}

// ---------------------------------------------------------------------------
// Fused flash attention: m16 warp tiles, 2 CTA/SM, 3-stage cp.async ring,
// ONE __syncthreads per j-tile. fp16 exp (ex2.approx.f16x2) -> P fragments;
// row sums via ones-MMA.  (Unchanged from best-passing version.)
// ---------------------------------------------------------------------------
#define F_VOFF  5120                 // K tile bytes (64 x pitch40 fp16)
#define F_STG   23552                // + V tile (128 x pitch72 fp16)
#define F_Q     70656                // 3 stages
#define F_SMEM  80896                // F_Q + 10240 (>= sO 67584)

__global__ __launch_bounds__(256, 2)
void fused_attn(const __half* __restrict__ QT, const __half* __restrict__ KT,
                const __half* __restrict__ VH,
                const float* __restrict__ X, const float* __restrict__ gamma,
                float* __restrict__ OUT)
{
    extern __shared__ char smem[];
    const uint32_t sbase = smem_u32(smem);
    const int tid = threadIdx.x, wid = tid >> 5, lane = tid & 31;
    const int mi = lane >> 3, row8 = lane & 7;
    const int i0 = blockIdx.x * 128;
    const int c0 = blockIdx.y * 128;
    const int b  = blockIdx.z;

    const __half* qg = QT + (size_t)b * WW * CQ;
    const __half* kg = KT + (size_t)b * WW * CQ;
    const __half* vhg = VH + (size_t)b * CH * WW + (size_t)c0 * WW;
    const float* xb = X + (size_t)b * CH * WW;
    float* ob = OUT + (size_t)b * CH * WW;

    auto stage = [&](int jt, int st) {
        const int j0 = jt * 64;
        const uint32_t sb = sbase + st * F_STG;
        {
            int r = tid >> 2, c8 = (tid & 3) * 8;
            cp16(sb + (uint32_t)(r * 40 + c8) * 2, kg + (size_t)(j0 + r) * CQ + c8);
        }
        #pragma unroll
        for (int it = 0; it < 4; it++) {
            int u = tid + 256 * it;                      // 0..1023 = 128x8 chunks
            int r = u >> 3, c8 = (u & 7) * 8;
            cp16(sb + F_VOFF + (uint32_t)(r * 72 + c8) * 2, vhg + (size_t)r * WW + j0 + c8);
        }
    };

    stage(0, 0);
    asm volatile("cp.async.commit_group;");
    stage(1, 1);
    asm volatile("cp.async.commit_group;");

    // load q tile (plain stores)
    #pragma unroll
    for (int it = 0; it < 2; it++) {
        int u = tid + 256 * it;
        int r = u >> 2, c8 = (u & 3) * 8;
        *(uint4*)(smem + F_Q + (uint32_t)(r * 40 + c8) * 2) =
            *(const uint4*)(qg + (size_t)(i0 + r) * CQ + c8);
    }
    __syncthreads();

    // cache q fragments (loop-invariant)
    uint32_t qa[8];
    #pragma unroll
    for (int kk = 0; kk < 2; kk++) {
        const uint32_t offA = (uint32_t)((wid * 16 + (mi & 1) * 8 + row8) * 40
                                         + kk * 16 + (mi >> 1) * 8) * 2;
        ldsm_x4(qa[kk*4+0], qa[kk*4+1], qa[kk*4+2], qa[kk*4+3], sbase + F_Q + offA);
    }

    const uint32_t ONES2 = 0x3C003C00u;          // half2(1.0, 1.0)
    const uint32_t ones_b[2] = {ONES2, ONES2};   // all-ones B fragment (n8 x k16)

    float o_[16][4] = {};
    float lacc[4] = {};                          // row-sum C frag (cols identical)
    float m0 = -1e30f, m1 = -1e30f;

    int st = 0;
    for (int jt = 0; jt < 32; jt++) {
        if (jt < 31) {
            asm volatile("cp.async.wait_group 1;");
        } else {
            asm volatile("cp.async.wait_group 0;");
        }
        __syncthreads();                         // single barrier per iteration

        // prefetch jt+2 into the ring slot consumed two iterations ago
        if (jt < 30) {
            int st2 = st + 2; if (st2 >= 3) st2 -= 3;
            stage(jt + 2, st2);
            asm volatile("cp.async.commit_group;");
        }

        const uint32_t aK = sbase + st * F_STG;
        const uint32_t aV = aK + F_VOFF;

        // ---- scores for all 64 j: single-term fp16 ----
        float s_[8][4] = {};
        #pragma unroll
        for (int kk = 0; kk < 2; kk++) {
            #pragma unroll
            for (int ntp = 0; ntp < 4; ntp++) {
                uint32_t off = (uint32_t)((ntp * 16 + (mi >> 1) * 8 + row8) * 40
                                          + kk * 16 + (mi & 1) * 8) * 2;
                uint32_t bk[4];
                ldsm_x4(bk[0], bk[1], bk[2], bk[3], aK + off);
                mma_fp16(s_[2*ntp],   &qa[kk*4], &bk[0]);
                mma_fp16(s_[2*ntp+1], &qa[kk*4], &bk[2]);
            }
        }

        // ---- running max (log2 domain) + rescale-skip ----
        float ml0 = -1e30f, ml1 = -1e30f;
        #pragma unroll
        for (int nt = 0; nt < 8; nt++) {
            ml0 = fmaxf(ml0, fmaxf(s_[nt][0], s_[nt][1]));
            ml1 = fmaxf(ml1, fmaxf(s_[nt][2], s_[nt][3]));
        }
        ml0 = fmaxf(ml0, __shfl_xor_sync(0xffffffffu, ml0, 1));
        ml0 = fmaxf(ml0, __shfl_xor_sync(0xffffffffu, ml0, 2));
        ml1 = fmaxf(ml1, __shfl_xor_sync(0xffffffffu, ml1, 1));
        ml1 = fmaxf(ml1, __shfl_xor_sync(0xffffffffu, ml1, 2));
        const float mn0 = fmaxf(m0, ml0), mn1 = fmaxf(m1, ml1);
        const bool nochg = __all_sync(0xffffffffu, (mn0 == m0) && (mn1 == m1));

        if (!nochg) {
            const float sc0 = ex2(m0 - mn0), sc1 = ex2(m1 - mn1);
            lacc[0] *= sc0;  lacc[1] *= sc0;
            lacc[2] *= sc1;  lacc[3] *= sc1;
            #pragma unroll
            for (int nt = 0; nt < 16; nt++) {
                o_[nt][0] *= sc0;  o_[nt][1] *= sc0;
                o_[nt][2] *= sc1;  o_[nt][3] *= sc1;
            }
        }
        m0 = mn0; m1 = mn1;

        // ---- P = exp2(s - m) via f16x2 MUFU -> A fragments directly ----
        uint32_t pa[4][4];
        #pragma unroll
        for (int ks = 0; ks < 4; ks++) {
            #pragma unroll
            for (int t = 0; t < 2; t++) {
                const int nt = 2 * ks + t;
                pa[ks][2*t]   = ex2_f16x2(cvt_f16x2(s_[nt][0] - mn0, s_[nt][1] - mn0));
                pa[ks][2*t+1] = ex2_f16x2(cvt_f16x2(s_[nt][2] - mn1, s_[nt][3] - mn1));
            }
            // row-sum accumulate: lacc += P(ks) @ ones
            mma_fp16(lacc, pa[ks], ones_b);
        }

        // ---- PV: O += P(fp16) V(fp16), 4 k-steps ----
        #pragma unroll
        for (int ks = 0; ks < 4; ks++) {
            #pragma unroll
            for (int ntp = 0; ntp < 8; ntp++) {
                uint32_t off = (uint32_t)((ntp * 16 + (mi >> 1) * 8 + row8) * 72
                                          + ks * 16 + (mi & 1) * 8) * 2;
                uint32_t bv[4];
                ldsm_x4(bv[0], bv[1], bv[2], bv[3], aV + off);
                mma_fp16(o_[2*ntp],   pa[ks], &bv[0]);
                mma_fp16(o_[2*ntp+1], pa[ks], &bv[2]);
            }
        }

        if (++st == 3) st = 0;
    }

    // ---- epilogue: normalize (lacc cols already hold full row sums) ----
    const float inv0 = 1.f / lacc[0], inv1 = 1.f / lacc[2];

    __syncthreads();                             // all warps done with ring before sO reuse
    float* sO = (float*)smem;            // [c 128][i 128] pitch 132
    const int rA = wid * 16 + (lane >> 2), rB = rA + 8;
    #pragma unroll
    for (int nt = 0; nt < 16; nt++) {
        const int c = nt * 8 + (lane & 3) * 2;
        sO[c * 132 + rA]       = o_[nt][0] * inv0;
        sO[(c + 1) * 132 + rA] = o_[nt][1] * inv0;
        sO[c * 132 + rB]       = o_[nt][2] * inv1;
        sO[(c + 1) * 132 + rB] = o_[nt][3] * inv1;
    }
    __syncthreads();

    const float g = gamma[0];
    #pragma unroll
    for (int it = 0; it < 16; it++) {
        int u = tid + 256 * it;               // 0..4095
        int r = u >> 5, c4 = (u & 31) * 4;
        float4 v4 = *(float4*)&sO[r * 132 + c4];
        size_t go = (size_t)(c0 + r) * WW + i0 + c4;
        float4 xv = *(const float4*)(xb + go);
        v4.x = g * v4.x + xv.x;
        v4.y = g * v4.y + xv.y;
        v4.z = g * v4.z + xv.z;
        v4.w = g * v4.w + xv.w;
        *(float4*)(ob + go) = v4;
    }
}

// ---------------------------------------------------------------------------
extern "C" void kernel_launch(void* const* d_in, const int* in_sizes, int n_in,
                              void* d_out, int out_size)
{
    const float* x     = (const float*)d_in[0];
    const float* wq    = (const float*)d_in[1];
    const float* bq    = (const float*)d_in[2];
    const float* wk    = (const float*)d_in[3];
    const float* bk    = (const float*)d_in[4];
    const float* wv    = (const float*)d_in[5];
    const float* bv    = (const float*)d_in[6];
    const float* gamma = (const float*)d_in[7];
    float* out = (float*)d_out;

    __half *vh, *qt, *kt, *xt, *wqd, *wkd, *wvd;
    cudaGetSymbolAddress((void**)&vh, g_vh);
    cudaGetSymbolAddress((void**)&qt, g_qt);
    cudaGetSymbolAddress((void**)&kt, g_kt);
    cudaGetSymbolAddress((void**)&xt, g_xt);
    cudaGetSymbolAddress((void**)&wqd, g_wq);
    cudaGetSymbolAddress((void**)&wkd, g_wk);
    cudaGetSymbolAddress((void**)&wvd, g_wv);

    // 1. convert all weights to fp16 (one launch)
    convert_weights<<<(2 * CQ * CH + CH * CH) / 256, 256>>>(wq, wk, wv, wqd, wkd, wvd);

    // 2. transpose x -> single fp16 x^T
    transpose_x<<<dim3(WW / 32, CH / 32, BATCH), 256>>>(x, xt);

    // 3. q/k projections (BK=64, cp.async 2-stage)
    cudaFuncSetAttribute(proj_qk, cudaFuncAttributeMaxDynamicSharedMemorySize, QK_SMEM);
    proj_qk<<<dim3(WW / 128, 2, BATCH), 256, QK_SMEM>>>(wqd, wkd, bq, bk, xt, qt, kt);

    // 4. v projection (BK=64, cp.async 2-stage)
    cudaFuncSetAttribute(proj_v, cudaFuncAttributeMaxDynamicSharedMemorySize, PV_SMEM);
    proj_v<<<dim3(WW / 128, CH / 128, BATCH), 256, PV_SMEM>>>(wvd, bv, xt, vh);

    // 5. fused attention (3-stage ring, single barrier per j-tile)
    cudaFuncSetAttribute(fused_attn, cudaFuncAttributeMaxDynamicSharedMemorySize, F_SMEM);
    fused_attn<<<dim3(WW / 128, CH / 128, BATCH), 256, F_SMEM>>>(
        qt, kt, vh, x, gamma, out);
}